// round 13
// baseline (speedup 1.0000x reference)
#include <cuda_runtime.h>
#include <math.h>

#define DEV_INLINE __device__ __forceinline__

// ---------------- problem constants ----------------
constexpr int cB = 2, cN = 512, cF = 1024, cH = 4, cDH = 256;
constexpr int cAH = 256, cHID = 512, cOUT = 128, cNC = 10;
constexpr int NN = cN * cN;               // 262144
constexpr int KSEL = 209715;              // int(0.8 * 512 * 512)
constexpr int RANK_SEL = NN - KSEL;       // 52429

// ---------------- scratch layout ----------------
constexpr size_t OFF_HP    = 0;
constexpr size_t OFF_ALPHA = OFF_HP    + (size_t)cB * cN * cF;
constexpr size_t OFF_NF    = OFF_ALPHA + (size_t)cB * cH * cN * cN;
constexpr size_t OFF_PI    = OFF_NF    + (size_t)cB * cN * cF;
constexpr size_t OFF_PJ    = OFF_PI    + (size_t)cB * cN * cAH;
constexpr size_t OFF_ES    = OFF_PJ    + (size_t)cB * cN * cAH;
constexpr size_t OFF_ADJ   = OFF_ES    + (size_t)cB * NN;
constexpr size_t OFF_H1    = OFF_ADJ   + (size_t)cB * NN;
constexpr size_t OFF_G1    = OFF_H1    + (size_t)cB * cN * cF;
constexpr size_t OFF_H2    = OFF_G1    + (size_t)cB * cN * cHID;
constexpr size_t OFF_G2    = OFF_H2    + (size_t)cB * cN * cHID;
constexpr size_t OFF_SI    = OFF_G2    + (size_t)cB * cN * cOUT;
constexpr size_t OFF_SJ    = OFF_SI    + (size_t)cB * cH * cN;
constexpr size_t OFF_PART  = OFF_SJ    + (size_t)cB * cH * cN;
constexpr size_t OFF_RED   = OFF_PART  + (size_t)cB * 256;
constexpr size_t OFF_BN1   = OFF_RED   + (size_t)cB * 8;
constexpr size_t OFF_BN2   = OFF_BN1   + (size_t)2 * cHID;
constexpr size_t OFF_BNP   = OFF_BN2   + (size_t)2 * cOUT;
constexpr size_t BUF_TOTAL = OFF_BNP   + (size_t)2 * cHID;

__device__ float    g_buf[BUF_TOTAL];
__device__ unsigned g_hist2[cB * 2048];
__device__ unsigned g_prefix[cB];
__device__ int      g_rank[cB];
__device__ unsigned g_maxkey[cB];
__device__ int      g_cnt[cB];

// ---------------- order-preserving float<->key transform ----------------
DEV_INLINE unsigned okey(float f) {
    int u = __float_as_int(f);
    return (unsigned)(u ^ ((u >> 31) | 0x80000000));
}
DEV_INLINE float okey_dec(unsigned k) {
    unsigned u = (k & 0x80000000u) ? (k ^ 0x80000000u) : ~k;
    return __uint_as_float(u);
}

// ---------------- reductions ----------------
struct SumOp { DEV_INLINE float operator()(float a, float b) const { return a + b; } };
struct MaxOp { DEV_INLINE float operator()(float a, float b) const { return fmaxf(a, b); } };

template <typename Op>
DEV_INLINE float blockReduceF(float v, Op op, float init) {
    __shared__ float sh[32];
    __syncthreads();
    int lane = threadIdx.x & 31, w = threadIdx.x >> 5;
#pragma unroll
    for (int o = 16; o; o >>= 1) v = op(v, __shfl_down_sync(0xffffffffu, v, o));
    if (lane == 0) sh[w] = v;
    __syncthreads();
    int nw = (blockDim.x + 31) >> 5;
    v = (threadIdx.x < nw) ? sh[threadIdx.x] : init;
    if (w == 0) {
#pragma unroll
        for (int o = 16; o; o >>= 1) v = op(v, __shfl_down_sync(0xffffffffu, v, o));
        if (lane == 0) sh[0] = v;
    }
    __syncthreads();
    return sh[0];
}

// ---------------- bf16 split helpers ----------------
DEV_INLINE unsigned pack_bf2(float f_even, float f_odd) {
    unsigned r;
    asm("cvt.rn.bf16x2.f32 %0, %1, %2;" : "=r"(r) : "f"(f_odd), "f"(f_even));
    return r;
}
DEV_INLINE void split2(float f0, float f1, unsigned& hi, unsigned& lo) {
    hi = pack_bf2(f0, f1);
    float h0 = __uint_as_float(hi << 16);
    float h1 = __uint_as_float(hi & 0xFFFF0000u);
    lo = pack_bf2(f0 - h0, f1 - h1);
}

DEV_INLINE void mma_bf16(float* c, unsigned a0, unsigned a1, unsigned a2, unsigned a3,
                         unsigned b0, unsigned b1) {
    asm volatile(
        "mma.sync.aligned.m16n8k16.row.col.f32.bf16.bf16.f32 "
        "{%0,%1,%2,%3}, {%4,%5,%6,%7}, {%8,%9}, {%0,%1,%2,%3};\n"
        : "+f"(c[0]), "+f"(c[1]), "+f"(c[2]), "+f"(c[3])
        : "r"(a0), "r"(a1), "r"(a2), "r"(a3), "r"(b0), "r"(b1));
}

// ---------------- tensor-core GEMM (3xBF16 split) — EXACT R8/282.7us code ---
constexpr int SMP2 = 68;

__global__ __launch_bounds__(256) void gemm_tc(
    const float* __restrict__ A, int lda, long long sA1, long long sA2,
    const float* __restrict__ B, int ldb, long long sB1, long long sB2,
    float* __restrict__ C, int ldc, long long sC1, long long sC2,
    int M, int Nd, int K, int HH,
    const float* __restrict__ bias, int bias_z, int b_nk) {
    __shared__ uint2 As[16][SMP2];
    __shared__ uint2 Bs[16][SMP2];
    int z = blockIdx.z, z1 = z / HH, z2 = z % HH;
    A += (size_t)z1 * sA1 + (size_t)z2 * sA2;
    B += (size_t)z1 * sB1 + (size_t)z2 * sB2;
    C += (size_t)z1 * sC1 + (size_t)z2 * sC2;
    int tid = threadIdx.x;
    int m0 = blockIdx.y * 64, n0 = blockIdx.x * 64;
    int lane = tid & 31, wid = tid >> 5;
    int wm = (wid >> 2) * 32, wn = (wid & 3) * 16;
    int tg = lane & 3, gp = lane >> 2;
    float acc[2][2][4] = {};
    const float* Ag = A + (size_t)m0 * lda;
    const float* Bg_nt = B + (size_t)n0 * ldb;

    float4 pa[2], pb[2];

    auto loadA = [&](int k0) {
#pragma unroll
        for (int it = 0; it < 2; it++) {
            int idx = tid + it * 256;
            int r = idx >> 3, c4 = idx & 7;
            pa[it] = *reinterpret_cast<const float4*>(Ag + (size_t)r * lda + k0 + c4 * 4);
        }
    };
    auto storeA = [&]() {
#pragma unroll
        for (int it = 0; it < 2; it++) {
            int idx = tid + it * 256;
            int r = idx >> 3, kp = (idx & 7) * 2;
            unsigned h0, l0, h1, l1;
            split2(pa[it].x, pa[it].y, h0, l0);
            split2(pa[it].z, pa[it].w, h1, l1);
            As[kp][r] = make_uint2(h0, l0);
            As[kp + 1][r] = make_uint2(h1, l1);
        }
    };
    auto loadB = [&](int k0) {
        if (b_nk) {
#pragma unroll
            for (int it = 0; it < 2; it++) {
                int idx = tid + it * 256;
                int r = idx >> 3, c4 = idx & 7;
                pb[it] = *reinterpret_cast<const float4*>(Bg_nt + (size_t)r * ldb + k0 + c4 * 4);
            }
        } else {
            int kp = tid >> 4, nc = (tid & 15) * 4;
            pb[0] = *reinterpret_cast<const float4*>(B + (size_t)(k0 + 2 * kp) * ldb + n0 + nc);
            pb[1] = *reinterpret_cast<const float4*>(B + (size_t)(k0 + 2 * kp + 1) * ldb + n0 + nc);
        }
    };
    auto storeB = [&]() {
        if (b_nk) {
#pragma unroll
            for (int it = 0; it < 2; it++) {
                int idx = tid + it * 256;
                int r = idx >> 3, kp = (idx & 7) * 2;
                unsigned h0, l0, h1, l1;
                split2(pb[it].x, pb[it].y, h0, l0);
                split2(pb[it].z, pb[it].w, h1, l1);
                Bs[kp][r] = make_uint2(h0, l0);
                Bs[kp + 1][r] = make_uint2(h1, l1);
            }
        } else {
            int kp = tid >> 4, nc = (tid & 15) * 4;
            float fe[4] = {pb[0].x, pb[0].y, pb[0].z, pb[0].w};
            float fo[4] = {pb[1].x, pb[1].y, pb[1].z, pb[1].w};
#pragma unroll
            for (int j = 0; j < 4; j++) {
                unsigned h, l;
                split2(fe[j], fo[j], h, l);
                Bs[kp][nc + j] = make_uint2(h, l);
            }
        }
    };

    loadA(0);
    loadB(0);
    for (int k0 = 0; k0 < K; k0 += 32) {
        storeA();
        storeB();
        __syncthreads();
        if (k0 + 32 < K) { loadA(k0 + 32); loadB(k0 + 32); }
#pragma unroll
        for (int ks = 0; ks < 16; ks += 8) {
            uint2 af[2][4], bf[2][2];
#pragma unroll
            for (int mt = 0; mt < 2; mt++) {
                int m = wm + mt * 16 + gp;
                af[mt][0] = As[ks + tg][m];     af[mt][1] = As[ks + tg][m + 8];
                af[mt][2] = As[ks + tg + 4][m]; af[mt][3] = As[ks + tg + 4][m + 8];
            }
#pragma unroll
            for (int nt = 0; nt < 2; nt++) {
                int n = wn + nt * 8 + gp;
                bf[nt][0] = Bs[ks + tg][n];
                bf[nt][1] = Bs[ks + tg + 4][n];
            }
            // hi*hi
#pragma unroll
            for (int nt = 0; nt < 2; nt++)
#pragma unroll
                for (int mt = 0; mt < 2; mt++)
                    mma_bf16(acc[mt][nt], af[mt][0].x, af[mt][1].x, af[mt][2].x, af[mt][3].x,
                             bf[nt][0].x, bf[nt][1].x);
            // lo*hi
#pragma unroll
            for (int nt = 0; nt < 2; nt++)
#pragma unroll
                for (int mt = 0; mt < 2; mt++)
                    mma_bf16(acc[mt][nt], af[mt][0].y, af[mt][1].y, af[mt][2].y, af[mt][3].y,
                             bf[nt][0].x, bf[nt][1].x);
            // hi*lo
#pragma unroll
            for (int nt = 0; nt < 2; nt++)
#pragma unroll
                for (int mt = 0; mt < 2; mt++)
                    mma_bf16(acc[mt][nt], af[mt][0].x, af[mt][1].x, af[mt][2].x, af[mt][3].x,
                             bf[nt][0].y, bf[nt][1].y);
        }
        __syncthreads();
    }
    bool useb = (bias != nullptr) && (z2 < bias_z);
#pragma unroll
    for (int mt = 0; mt < 2; mt++) {
        int r = m0 + wm + mt * 16 + gp;
#pragma unroll
        for (int nt = 0; nt < 2; nt++) {
            int ncol = n0 + wn + nt * 8 + tg * 2;
            float b0v = useb ? bias[ncol] : 0.f;
            float b1v = useb ? bias[ncol + 1] : 0.f;
            C[(size_t)r * ldc + ncol]           = acc[mt][nt][0] + b0v;
            C[(size_t)r * ldc + ncol + 1]       = acc[mt][nt][1] + b1v;
            C[(size_t)(r + 8) * ldc + ncol]     = acc[mt][nt][2] + b0v;
            C[(size_t)(r + 8) * ldc + ncol + 1] = acc[mt][nt][3] + b1v;
        }
    }
}

// ---------------- CLONE: t2 GEMM with fused bn1-affine+relu on A ------------
__global__ __launch_bounds__(256) void gemm_tc_bn(
    const float* __restrict__ A, int lda,
    const float* __restrict__ B, int ldb,
    float* __restrict__ C, int ldc,
    int M, int Nd, int K,
    const float* __restrict__ a_sc, const float* __restrict__ a_sh) {
    __shared__ uint2 As[16][SMP2];
    __shared__ uint2 Bs[16][SMP2];
    int tid = threadIdx.x;
    int m0 = blockIdx.y * 64, n0 = blockIdx.x * 64;
    int lane = tid & 31, wid = tid >> 5;
    int wm = (wid >> 2) * 32, wn = (wid & 3) * 16;
    int tg = lane & 3, gp = lane >> 2;
    float acc[2][2][4] = {};
    const float* Ag = A + (size_t)m0 * lda;
    const float* Bg = B + (size_t)n0 * ldb;

    float4 pa[2], pb[2];

    auto loadA = [&](int k0) {
#pragma unroll
        for (int it = 0; it < 2; it++) {
            int idx = tid + it * 256;
            int r = idx >> 3, c4 = idx & 7;
            pa[it] = *reinterpret_cast<const float4*>(Ag + (size_t)r * lda + k0 + c4 * 4);
        }
    };
    auto storeA = [&](int k0) {
#pragma unroll
        for (int it = 0; it < 2; it++) {
            int idx = tid + it * 256;
            int r = idx >> 3, kp = (idx & 7) * 2;
            int k = k0 + (idx & 7) * 4;
            float4 s4 = *reinterpret_cast<const float4*>(a_sc + k);
            float4 h4 = *reinterpret_cast<const float4*>(a_sh + k);
            float v0 = fmaxf(pa[it].x * s4.x + h4.x, 0.f);
            float v1 = fmaxf(pa[it].y * s4.y + h4.y, 0.f);
            float v2 = fmaxf(pa[it].z * s4.z + h4.z, 0.f);
            float v3 = fmaxf(pa[it].w * s4.w + h4.w, 0.f);
            unsigned h0, l0, h1, l1;
            split2(v0, v1, h0, l0);
            split2(v2, v3, h1, l1);
            As[kp][r] = make_uint2(h0, l0);
            As[kp + 1][r] = make_uint2(h1, l1);
        }
    };
    auto loadB = [&](int k0) {
#pragma unroll
        for (int it = 0; it < 2; it++) {
            int idx = tid + it * 256;
            int r = idx >> 3, c4 = idx & 7;
            pb[it] = *reinterpret_cast<const float4*>(Bg + (size_t)r * ldb + k0 + c4 * 4);
        }
    };
    auto storeB = [&]() {
#pragma unroll
        for (int it = 0; it < 2; it++) {
            int idx = tid + it * 256;
            int r = idx >> 3, kp = (idx & 7) * 2;
            unsigned h0, l0, h1, l1;
            split2(pb[it].x, pb[it].y, h0, l0);
            split2(pb[it].z, pb[it].w, h1, l1);
            Bs[kp][r] = make_uint2(h0, l0);
            Bs[kp + 1][r] = make_uint2(h1, l1);
        }
    };

    loadA(0);
    loadB(0);
    for (int k0 = 0; k0 < K; k0 += 32) {
        storeA(k0);
        storeB();
        __syncthreads();
        if (k0 + 32 < K) { loadA(k0 + 32); loadB(k0 + 32); }
#pragma unroll
        for (int ks = 0; ks < 16; ks += 8) {
            uint2 af[2][4], bf[2][2];
#pragma unroll
            for (int mt = 0; mt < 2; mt++) {
                int m = wm + mt * 16 + gp;
                af[mt][0] = As[ks + tg][m];     af[mt][1] = As[ks + tg][m + 8];
                af[mt][2] = As[ks + tg + 4][m]; af[mt][3] = As[ks + tg + 4][m + 8];
            }
#pragma unroll
            for (int nt = 0; nt < 2; nt++) {
                int n = wn + nt * 8 + gp;
                bf[nt][0] = Bs[ks + tg][n];
                bf[nt][1] = Bs[ks + tg + 4][n];
            }
#pragma unroll
            for (int nt = 0; nt < 2; nt++)
#pragma unroll
                for (int mt = 0; mt < 2; mt++)
                    mma_bf16(acc[mt][nt], af[mt][0].x, af[mt][1].x, af[mt][2].x, af[mt][3].x,
                             bf[nt][0].x, bf[nt][1].x);
#pragma unroll
            for (int nt = 0; nt < 2; nt++)
#pragma unroll
                for (int mt = 0; mt < 2; mt++)
                    mma_bf16(acc[mt][nt], af[mt][0].y, af[mt][1].y, af[mt][2].y, af[mt][3].y,
                             bf[nt][0].x, bf[nt][1].x);
#pragma unroll
            for (int nt = 0; nt < 2; nt++)
#pragma unroll
                for (int mt = 0; mt < 2; mt++)
                    mma_bf16(acc[mt][nt], af[mt][0].x, af[mt][1].x, af[mt][2].x, af[mt][3].x,
                             bf[nt][0].y, bf[nt][1].y);
        }
        __syncthreads();
    }
#pragma unroll
    for (int mt = 0; mt < 2; mt++) {
        int r = m0 + wm + mt * 16 + gp;
#pragma unroll
        for (int nt = 0; nt < 2; nt++) {
            int ncol = n0 + wn + nt * 8 + tg * 2;
            C[(size_t)r * ldc + ncol]           = acc[mt][nt][0];
            C[(size_t)r * ldc + ncol + 1]       = acc[mt][nt][1];
            C[(size_t)(r + 8) * ldc + ncol]     = acc[mt][nt][2];
            C[(size_t)(r + 8) * ldc + ncol + 1] = acc[mt][nt][3];
        }
    }
}

// ---------------- attention scores s_i, s_j ----------------
__global__ void si_sj2(const float* __restrict__ hp, const float* __restrict__ attw,
                       float* __restrict__ si, float* __restrict__ sj) {
    int bn = blockIdx.x;
    int b = bn >> 9, n = bn & 511;
    int t = threadIdx.x, w = t >> 5, l = t & 31;
    int h = w >> 1, part = w & 1;
    const float* row = hp + (size_t)bn * cF + h * cDH;
    const float* aw = attw + h * 2 * cDH + part * cDH;
    float s = 0.f;
#pragma unroll
    for (int q = 0; q < 8; q++) {
        int d = q * 32 + l;
        s += row[d] * aw[d];
    }
#pragma unroll
    for (int o = 16; o; o >>= 1) s += __shfl_down_sync(0xffffffffu, s, o);
    if (l == 0) {
        float* dst = part ? sj : si;
        dst[((size_t)(b * cH + h)) * cN + n] = s;
    }
}

// ---------------- per-row attention softmax ----------------
__global__ void attn_softmax(const float* __restrict__ si, const float* __restrict__ sj,
                             float* __restrict__ alpha) {
    int id = blockIdx.x;
    int i = id & 511, bh = id >> 9;
    float s_i = si[(size_t)bh * cN + i];
    const float* sjr = sj + (size_t)bh * cN;
    int t = threadIdx.x;
    float x0 = s_i + sjr[t];
    float x1 = s_i + sjr[t + 256];
    float e0 = x0 >= 0.f ? x0 : 0.2f * x0;
    float e1 = x1 >= 0.f ? x1 : 0.2f * x1;
    float m = blockReduceF(fmaxf(e0, e1), MaxOp(), -1e30f);
    float p0 = expf(e0 - m), p1 = expf(e1 - m);
    float s = blockReduceF(p0 + p1, SumOp(), 0.f);
    float inv = 1.f / s;
    float* arow = alpha + (size_t)id * cN;
    arow[t] = p0 * inv;
    arow[t + 256] = p1 * inv;
}

// ---------------- edge MLP + global-max epilogue ----------------
__global__ void edge_kernel(const float* __restrict__ pi, const float* __restrict__ pj,
                            const float* __restrict__ w2, const float* __restrict__ b2,
                            float* __restrict__ es) {
    __shared__ float pis[32][65];
    __shared__ float pjs[32][65];
    __shared__ float w2s[32];
    int b = blockIdx.z;
    int i0 = blockIdx.y * 64, j0 = blockIdx.x * 64;
    int tid = threadIdx.x;
    int tx = tid & 15, ty = tid >> 4;
    float acc[4][4] = {};
    for (int a0 = 0; a0 < cAH; a0 += 32) {
        for (int idx = tid; idx < 64 * 32; idx += 256) {
            int a = idx & 31, r = idx >> 5;
            pis[a][r] = pi[((size_t)(b * cN + i0 + r)) * cAH + a0 + a];
            pjs[a][r] = pj[((size_t)(b * cN + j0 + r)) * cAH + a0 + a];
        }
        if (tid < 32) w2s[tid] = w2[a0 + tid];
        __syncthreads();
#pragma unroll 8
        for (int a = 0; a < 32; a++) {
            float w = w2s[a];
            float pv[4], qv[4];
#pragma unroll
            for (int u = 0; u < 4; u++) pv[u] = pis[a][ty + 16 * u];
#pragma unroll
            for (int v = 0; v < 4; v++) qv[v] = pjs[a][tx + 16 * v];
#pragma unroll
            for (int u = 0; u < 4; u++)
#pragma unroll
                for (int v = 0; v < 4; v++)
                    acc[u][v] += fmaxf(pv[u] + qv[v], 0.f) * w;
        }
        __syncthreads();
    }
    float bb = b2[0];
    float lmax = -1e30f;
#pragma unroll
    for (int u = 0; u < 4; u++)
#pragma unroll
        for (int v = 0; v < 4; v++) {
            float val = acc[u][v] + bb;
            es[((size_t)b * cN + i0 + ty + 16 * u) * cN + j0 + tx + 16 * v] = val;
            lmax = fmaxf(lmax, val);
        }
    lmax = blockReduceF(lmax, MaxOp(), -1e30f);
    if (tid == 0) atomicMax(&g_maxkey[b], okey(lmax));
}

// ---------------- exact select: pass0 hist/scan + compact + tiny select -----
__global__ void sel_init() {
    int t = blockIdx.x * blockDim.x + threadIdx.x;
    if (t < cB * 2048) g_hist2[t] = 0;
    if (t < cB) { g_prefix[t] = 0; g_rank[t] = RANK_SEL; g_maxkey[t] = 0; g_cnt[t] = 0; }
}

__global__ void sel_hist_g(const float* __restrict__ es) {
    int b = blockIdx.y;
    __shared__ unsigned hist[2048];
    for (int i = threadIdx.x; i < 2048; i += 256) hist[i] = 0;
    __syncthreads();
    const float* data = es + (size_t)b * NN;
    int per = NN / gridDim.x;
    int base = blockIdx.x * per;
    for (int i = threadIdx.x; i < per; i += 256) {
        unsigned u = okey(data[base + i]);
        int bin = (int)(u >> 21);
        unsigned mask = __match_any_sync(0xffffffffu, bin);
        if ((threadIdx.x & 31) == (__ffs(mask) - 1))
            atomicAdd(&hist[bin], (unsigned)__popc(mask));
    }
    __syncthreads();
    for (int i = threadIdx.x; i < 2048; i += 256)
        if (hist[i]) atomicAdd(&g_hist2[b * 2048 + i], hist[i]);
}

__global__ void sel_step_g(float* __restrict__ red) {
    int b = blockIdx.x;
    int t = threadIdx.x;  // 256
    unsigned* hist = g_hist2 + (size_t)b * 2048;
    unsigned loc[8];
    unsigned psum = 0;
#pragma unroll
    for (int q = 0; q < 8; q++) { loc[q] = hist[t * 8 + q]; psum += loc[q]; }
    __shared__ unsigned sh[256];
    __shared__ int s_sel;
    __shared__ unsigned s_cum;
    sh[t] = psum;
    __syncthreads();
    if (t == 0) {
        int r = g_rank[b];
        unsigned cum = 0;
        int ti = 0;
        for (; ti < 255; ti++) {
            if (cum + sh[ti] > (unsigned)r) break;
            cum += sh[ti];
        }
        s_sel = ti;
        s_cum = cum;
    }
    __syncthreads();
    if (t == s_sel) {
        int r = g_rank[b];
        unsigned cum = s_cum;
        int bin = t * 8;
#pragma unroll
        for (int q = 0; q < 8; q++) {
            if (cum + loc[q] > (unsigned)r) { bin = t * 8 + q; break; }
            cum += loc[q];
        }
        g_rank[b] = r - (int)cum;
        g_prefix[b] = (unsigned)bin << 21;
    }
    __syncthreads();
    for (int i = t; i < 2048; i += 256) hist[i] = 0;  // re-zero for replay
}

__global__ void sel_compact(const float* __restrict__ es, float* __restrict__ cand) {
    int b = blockIdx.y;
    unsigned sel0 = g_prefix[b] >> 21;
    const float* data = es + (size_t)b * NN;
    float* cd = cand + (size_t)b * NN;
    int per = NN / gridDim.x;
    int base = blockIdx.x * per;
    for (int i = threadIdx.x; i < per; i += 256) {
        float v = data[base + i];
        if ((okey(v) >> 21) == sel0) {
            int pos = atomicAdd(&g_cnt[b], 1);
            cd[pos] = v;
        }
    }
}

// single block per batch: resolve remaining 21 bits over the candidate set
__global__ void sel_small(const float* __restrict__ cand, float* __restrict__ red) {
    int b = blockIdx.x;
    int t = threadIdx.x;  // 256
    int cnt = g_cnt[b];
    int r = g_rank[b];
    unsigned pre = g_prefix[b];
    const float* cd = cand + (size_t)b * NN;
    __shared__ unsigned hist[2048];
    __shared__ unsigned sh[256];
    __shared__ int s_sel;
    __shared__ unsigned s_cum;
    __shared__ int s_r;
    __shared__ int s_b1;
    int iters = (cnt + 255) >> 8;

    // phase A: bits 20..10 (2048 bins)
    for (int i = t; i < 2048; i += 256) hist[i] = 0;
    __syncthreads();
    for (int it = 0; it < iters; it++) {
        int i = it * 256 + t;
        int bin = -1;
        if (i < cnt) bin = (int)((okey(cd[i]) >> 10) & 0x7FFu);
        unsigned mask = __match_any_sync(0xffffffffu, bin);
        if (bin >= 0 && ((t & 31) == (__ffs(mask) - 1)))
            atomicAdd(&hist[bin], (unsigned)__popc(mask));
    }
    __syncthreads();
    {
        unsigned loc[8];
        unsigned psum = 0;
#pragma unroll
        for (int q = 0; q < 8; q++) { loc[q] = hist[t * 8 + q]; psum += loc[q]; }
        sh[t] = psum;
        __syncthreads();
        if (t == 0) {
            unsigned cum = 0;
            int ti = 0;
            for (; ti < 255; ti++) {
                if (cum + sh[ti] > (unsigned)r) break;
                cum += sh[ti];
            }
            s_sel = ti;
            s_cum = cum;
        }
        __syncthreads();
        if (t == s_sel) {
            unsigned cum = s_cum;
            int bin = t * 8;
#pragma unroll
            for (int q = 0; q < 8; q++) {
                if (cum + loc[q] > (unsigned)r) { bin = t * 8 + q; break; }
                cum += loc[q];
            }
            s_r = r - (int)cum;
            s_b1 = bin;
        }
    }
    __syncthreads();
    int r2 = s_r;
    unsigned b1 = (unsigned)s_b1;

    // phase B: bits 9..0 (1024 bins)
    for (int i = t; i < 1024; i += 256) hist[i] = 0;
    __syncthreads();
    for (int it = 0; it < iters; it++) {
        int i = it * 256 + t;
        int bin = -1;
        if (i < cnt) {
            unsigned u = okey(cd[i]);
            if (((u >> 10) & 0x7FFu) == b1) bin = (int)(u & 0x3FFu);
        }
        unsigned mask = __match_any_sync(0xffffffffu, bin);
        if (bin >= 0 && ((t & 31) == (__ffs(mask) - 1)))
            atomicAdd(&hist[bin], (unsigned)__popc(mask));
    }
    __syncthreads();
    {
        unsigned loc[4];
        unsigned psum = 0;
#pragma unroll
        for (int q = 0; q < 4; q++) { loc[q] = hist[t * 4 + q]; psum += loc[q]; }
        sh[t] = psum;
        __syncthreads();
        if (t == 0) {
            unsigned cum = 0;
            int ti = 0;
            for (; ti < 255; ti++) {
                if (cum + sh[ti] > (unsigned)r2) break;
                cum += sh[ti];
            }
            s_sel = ti;
            s_cum = cum;
        }
        __syncthreads();
        if (t == s_sel) {
            unsigned cum = s_cum;
            int bin = t * 4;
#pragma unroll
            for (int q = 0; q < 4; q++) {
                if (cum + loc[q] > (unsigned)r2) { bin = t * 4 + q; break; }
                cum += loc[q];
            }
            unsigned key = pre | (b1 << 10) | (unsigned)bin;
            red[b * 8 + 2] = __uint_as_float(key);
        }
    }
}

// ---------------- kept-sum + full-sum of exp(2(e-m)) in one pass ------------
__global__ void csum2_kernel(const float* __restrict__ es, const float* __restrict__ red,
                             float* __restrict__ part) {
    int b = blockIdx.y, seg = blockIdx.x;
    unsigned thr = __float_as_uint(red[b * 8 + 2]);
    float m = okey_dec(g_maxkey[b]);
    const float* p = es + (size_t)b * NN + seg * 2048;
    float sk = 0.f, sz = 0.f;
    for (int i = threadIdx.x; i < 2048; i += 256) {
        float v = p[i];
        float e = expf(2.f * (v - m));
        sz += e;
        if (okey(v) >= thr) sk += e;
    }
    sk = blockReduceF(sk, SumOp(), 0.f);
    sz = blockReduceF(sz, SumOp(), 0.f);
    if (threadIdx.x == 0) {
        part[b * 256 + seg] = sk;
        part[b * 256 + 128 + seg] = sz;
    }
}

__global__ void reduce2_kernel(const float* __restrict__ part, float* __restrict__ red) {
    int b = blockIdx.x;
    float v1 = part[b * 256 + threadIdx.x];
    float v2 = part[b * 256 + 128 + threadIdx.x];
    v1 = blockReduceF(v1, SumOp(), 0.f);
    v2 = blockReduceF(v2, SumOp(), 0.f);
    if (threadIdx.x == 0) {
        red[b * 8 + 3] = v1;  // S_kept
        red[b * 8 + 4] = v2;  // Z
    }
}

__global__ void adj_write(const float* __restrict__ es, const float* __restrict__ red,
                          float* __restrict__ adj) {
    size_t i = (size_t)blockIdx.x * blockDim.x + threadIdx.x;
    int b = (int)(i / NN);
    unsigned thr = __float_as_uint(red[b * 8 + 2]);
    float m = okey_dec(g_maxkey[b]);
    float inv = 1.f / (red[b * 8 + 3] + red[b * 8 + 4] * 1e-12f);
    float v = es[i];
    adj[i] = (okey(v) >= thr) ? expf(2.f * (v - m)) * inv : 0.f;
}

// ---------------- coalesced batchnorm stats (64 channels / block) -----------
__global__ void bn_statsC(const float* __restrict__ h, int C, float* __restrict__ stats) {
    int c0 = blockIdx.x * 64;
    int cl = threadIdx.x & 63, rg = threadIdx.x >> 6;  // 4 row groups
    double s = 0.0, s2 = 0.0;
    for (int r = rg; r < cB * cN; r += 4) {
        double v = (double)h[(size_t)r * C + c0 + cl];
        s += v;
        s2 += v * v;
    }
    __shared__ double sh_s[256], sh_q[256];
    sh_s[threadIdx.x] = s;
    sh_q[threadIdx.x] = s2;
    __syncthreads();
    if (rg == 0) {
        for (int q = 1; q < 4; q++) { s += sh_s[cl + 64 * q]; s2 += sh_q[cl + 64 * q]; }
        double m = s / (cB * cN);
        double var = s2 / (cB * cN) - m * m;
        stats[2 * (c0 + cl)] = (float)m;
        stats[2 * (c0 + cl) + 1] = (float)rsqrt(var + 1e-5);
    }
}

// fold bn stats + gamma/beta into per-channel scale/shift
__global__ void bn_prep(const float* __restrict__ stats, const float* __restrict__ ga,
                        const float* __restrict__ be, float* __restrict__ sc,
                        float* __restrict__ sh, int C) {
    int c = blockIdx.x * blockDim.x + threadIdx.x;
    if (c < C) {
        float s = stats[2 * c + 1] * ga[c];
        sc[c] = s;
        sh[c] = be[c] - stats[2 * c] * s;
    }
}

// ---------------- final ----------------
__global__ void final_kernel(const float* __restrict__ g2, const float* __restrict__ stats,
                             const float* __restrict__ ga, const float* __restrict__ be,
                             const float* __restrict__ clsw, const float* __restrict__ clsb,
                             float* __restrict__ out) {
    int b = blockIdx.x, c = threadIdx.x;
    float m = stats[2 * c], is = stats[2 * c + 1], gg = ga[c], bb = be[c];
    float s = 0.f;
    for (int n = 0; n < cN; n++) {
        float v = g2[((size_t)(b * cN + n)) * cOUT + c];
        v = (v - m) * is * gg + bb;
        s += fmaxf(v, 0.f);
    }
    __shared__ float feat[cOUT];
    feat[c] = s * (1.f / cN);
    __syncthreads();
    if (c < cNC) {
        float o = clsb[c];
        for (int q = 0; q < cOUT; q++) o += feat[q] * clsw[c * cOUT + q];
        out[b * cNC + c] = o;
    }
}

// ---------------- launch ----------------
extern "C" void kernel_launch(void* const* d_in, const int* in_sizes, int n_in,
                              void* d_out, int out_size) {
    const float* x      = (const float*)d_in[0];
    const float* Wg     = (const float*)d_in[1];
    const float* attn_w = (const float*)d_in[2];
    const float* W1     = (const float*)d_in[3];
    const float* b1     = (const float*)d_in[4];
    const float* w2     = (const float*)d_in[5];
    const float* b2     = (const float*)d_in[6];
    const float* gc1_w  = (const float*)d_in[7];
    const float* gc1_b  = (const float*)d_in[8];
    const float* bn1g   = (const float*)d_in[9];
    const float* bn1b   = (const float*)d_in[10];
    const float* gc2_w  = (const float*)d_in[11];
    const float* gc2_b  = (const float*)d_in[12];
    const float* bn2g   = (const float*)d_in[13];
    const float* bn2b   = (const float*)d_in[14];
    const float* clsw   = (const float*)d_in[15];
    const float* clsb   = (const float*)d_in[16];

    float* buf = nullptr;
    cudaGetSymbolAddress((void**)&buf, g_buf);
    float* hp    = buf + OFF_HP;
    float* alpha = buf + OFF_ALPHA;
    float* nf    = buf + OFF_NF;
    float* pi    = buf + OFF_PI;
    float* pj    = buf + OFF_PJ;
    float* es    = buf + OFF_ES;
    float* adj   = buf + OFF_ADJ;
    float* t1    = buf + OFF_H1;
    float* g1    = buf + OFF_G1;
    float* t2    = buf + OFF_H2;
    float* g2    = buf + OFF_G2;
    float* si    = buf + OFF_SI;
    float* sj    = buf + OFF_SJ;
    float* part  = buf + OFF_PART;
    float* red   = buf + OFF_RED;
    float* bn1s  = buf + OFF_BN1;
    float* bn2s  = buf + OFF_BN2;
    float* bnsc  = buf + OFF_BNP;
    float* bnsh  = buf + OFF_BNP + cHID;

    typedef long long ll;

    // 0) init select state (before edge_kernel's atomicMax)
    sel_init<<<16, 256>>>();
    // 1) hp = x @ Wg^T
    gemm_tc<<<dim3(cF / 64, (cB * cN) / 64, 1), 256>>>(
        x, cF, 0, 0, Wg, cF, 0, 0, hp, cF, 0, 0,
        cB * cN, cF, cF, 1, nullptr, 0, 1);
    // 2) s_i, s_j
    si_sj2<<<cB * cN, 256>>>(hp, attn_w, si, sj);
    // 3) attention softmax
    attn_softmax<<<cB * cH * cN, 256>>>(si, sj, alpha);
    // 4) node_feats = alpha @ hp (batched b,h)
    gemm_tc<<<dim3(cDH / 64, cN / 64, cB * cH), 256>>>(
        alpha, cN, (ll)cH * NN, (ll)NN,
        hp, cF, (ll)cN * cF, (ll)cDH,
        nf, cF, (ll)cN * cF, (ll)cDH,
        cN, cDH, cN, cH, nullptr, 0, 0);
    // 5) pi/pj fused (grid.z = 2)
    gemm_tc<<<dim3(cAH / 64, (cB * cN) / 64, 2), 256>>>(
        nf, cF, 0, 0,
        W1, 2 * cF, 0, (ll)cF,
        pi, cAH, 0, (ll)cB * cN * cAH,
        cB * cN, cAH, cF, 2, b1, 1, 1);
    // 6) edge scores + per-batch max
    edge_kernel<<<dim3(cN / 64, cN / 64, cB), 256>>>(pi, pj, w2, b2, es);
    // 7) exact order statistic: pass0 hist/scan, compact candidates (into adj
    //    region, free until adj_write), then tiny single-block select
    sel_hist_g<<<dim3(64, cB), 256>>>(es);
    sel_step_g<<<cB, 256>>>(red);
    sel_compact<<<dim3(64, cB), 256>>>(es, adj);
    sel_small<<<cB, 256>>>(adj, red);
    // 8) kept-sum + Z; adjacency write
    csum2_kernel<<<dim3(128, cB), 256>>>(es, red, part);
    reduce2_kernel<<<cB, 128>>>(part, red);
    adj_write<<<(cB * NN) / 256, 256>>>(es, red, adj);
    // 9) stage 1 (reassociated): t1 = nf @ gc1_w^T ; g1 = adj @ t1 + gc1_b
    gemm_tc<<<dim3(cHID / 64, (cB * cN) / 64, 1), 256>>>(
        nf, cF, 0, 0, gc1_w, cF, 0, 0, t1, cHID, 0, 0,
        cB * cN, cHID, cF, 1, nullptr, 0, 1);
    gemm_tc<<<dim3(cHID / 64, cN / 64, cB), 256>>>(
        adj, cN, (ll)NN, 0,
        t1, cHID, (ll)cN * cHID, 0,
        g1, cHID, (ll)cN * cHID, 0,
        cN, cHID, cN, 1, gc1_b, 1, 0);
    bn_statsC<<<cHID / 64, 256>>>(g1, cHID, bn1s);
    bn_prep<<<2, 256>>>(bn1s, bn1g, bn1b, bnsc, bnsh, cHID);
    // 10) stage 2 (reassociated): t2 = bnrelu(g1) @ gc2_w^T via clone,
    //     then g2 = adj @ t2 + gc2_b via untouched gemm_tc
    gemm_tc_bn<<<dim3(cOUT / 64, (cB * cN) / 64), 256>>>(
        g1, cHID, gc2_w, cHID, t2, cOUT,
        cB * cN, cOUT, cHID, bnsc, bnsh);
    gemm_tc<<<dim3(cOUT / 64, cN / 64, cB), 256>>>(
        adj, cN, (ll)NN, 0,
        t2, cOUT, (ll)cN * cOUT, 0,
        g2, cOUT, (ll)cN * cOUT, 0,
        cN, cOUT, cN, 1, gc2_b, 1, 0);
    bn_statsC<<<cOUT / 64, 256>>>(g2, cOUT, bn2s);
    // 11) final
    final_kernel<<<cB, 128>>>(g2, bn2s, bn2g, bn2b, clsw, clsb, (float*)d_out);
}

// round 14
// speedup vs baseline: 1.7501x; 1.7501x over previous
#include <cuda_runtime.h>
#include <math.h>

#define DEV_INLINE __device__ __forceinline__

// ---------------- problem constants ----------------
constexpr int cB = 2, cN = 512, cF = 1024, cH = 4, cDH = 256;
constexpr int cAH = 256, cHID = 512, cOUT = 128, cNC = 10;
constexpr int NN = cN * cN;               // 262144
constexpr int KSEL = 209715;              // int(0.8 * 512 * 512)
constexpr int RANK_SEL = NN - KSEL;       // 52429

// ---------------- scratch layout ----------------
constexpr size_t OFF_HP    = 0;
constexpr size_t OFF_ALPHA = OFF_HP    + (size_t)cB * cN * cF;
constexpr size_t OFF_NF    = OFF_ALPHA + (size_t)cB * cH * cN * cN;
constexpr size_t OFF_PI    = OFF_NF    + (size_t)cB * cN * cF;
constexpr size_t OFF_PJ    = OFF_PI    + (size_t)cB * cN * cAH;
constexpr size_t OFF_ES    = OFF_PJ    + (size_t)cB * cN * cAH;
constexpr size_t OFF_ADJ   = OFF_ES    + (size_t)cB * NN;
constexpr size_t OFF_H1    = OFF_ADJ   + (size_t)cB * NN;
constexpr size_t OFF_G1    = OFF_H1    + (size_t)cB * cN * cF;
constexpr size_t OFF_H2    = OFF_G1    + (size_t)cB * cN * cHID;
constexpr size_t OFF_G2    = OFF_H2    + (size_t)cB * cN * cHID;
constexpr size_t OFF_SI    = OFF_G2    + (size_t)cB * cN * cOUT;
constexpr size_t OFF_SJ    = OFF_SI    + (size_t)cB * cH * cN;
constexpr size_t OFF_PART  = OFF_SJ    + (size_t)cB * cH * cN;
constexpr size_t OFF_RED   = OFF_PART  + (size_t)cB * 256;
constexpr size_t OFF_BN1   = OFF_RED   + (size_t)cB * 8;
constexpr size_t OFF_BN2   = OFF_BN1   + (size_t)2 * cHID;
constexpr size_t OFF_BNP   = OFF_BN2   + (size_t)2 * cOUT;   // folded bn1 scale/shift
constexpr size_t BUF_TOTAL = OFF_BNP   + (size_t)2 * cHID;

__device__ float    g_buf[BUF_TOTAL];
__device__ unsigned g_hist2[cB * 2048];
__device__ unsigned g_prefix[cB];
__device__ int      g_rank[cB];
__device__ unsigned g_maxkey[cB];

// ---------------- order-preserving float<->key transform ----------------
DEV_INLINE unsigned okey(float f) {
    int u = __float_as_int(f);
    return (unsigned)(u ^ ((u >> 31) | 0x80000000));
}
DEV_INLINE float okey_dec(unsigned k) {
    unsigned u = (k & 0x80000000u) ? (k ^ 0x80000000u) : ~k;
    return __uint_as_float(u);
}

// ---------------- reductions ----------------
struct SumOp { DEV_INLINE float operator()(float a, float b) const { return a + b; } };
struct MaxOp { DEV_INLINE float operator()(float a, float b) const { return fmaxf(a, b); } };

template <typename Op>
DEV_INLINE float blockReduceF(float v, Op op, float init) {
    __shared__ float sh[32];
    __syncthreads();
    int lane = threadIdx.x & 31, w = threadIdx.x >> 5;
#pragma unroll
    for (int o = 16; o; o >>= 1) v = op(v, __shfl_down_sync(0xffffffffu, v, o));
    if (lane == 0) sh[w] = v;
    __syncthreads();
    int nw = (blockDim.x + 31) >> 5;
    v = (threadIdx.x < nw) ? sh[threadIdx.x] : init;
    if (w == 0) {
#pragma unroll
        for (int o = 16; o; o >>= 1) v = op(v, __shfl_down_sync(0xffffffffu, v, o));
        if (lane == 0) sh[0] = v;
    }
    __syncthreads();
    return sh[0];
}

DEV_INLINE double blockReduceD(double v) {
    __shared__ double shd[32];
    __syncthreads();
    int lane = threadIdx.x & 31, w = threadIdx.x >> 5;
#pragma unroll
    for (int o = 16; o; o >>= 1) v += __shfl_down_sync(0xffffffffu, v, o);
    if (lane == 0) shd[w] = v;
    __syncthreads();
    int nw = (blockDim.x + 31) >> 5;
    v = (threadIdx.x < nw) ? shd[threadIdx.x] : 0.0;
    if (w == 0) {
#pragma unroll
        for (int o = 16; o; o >>= 1) v += __shfl_down_sync(0xffffffffu, v, o);
        if (lane == 0) shd[0] = v;
    }
    __syncthreads();
    return shd[0];
}

// ---------------- bf16 split helpers ----------------
DEV_INLINE unsigned pack_bf2(float f_even, float f_odd) {
    unsigned r;
    asm("cvt.rn.bf16x2.f32 %0, %1, %2;" : "=r"(r) : "f"(f_odd), "f"(f_even));
    return r;
}
DEV_INLINE void split2(float f0, float f1, unsigned& hi, unsigned& lo) {
    hi = pack_bf2(f0, f1);
    float h0 = __uint_as_float(hi << 16);
    float h1 = __uint_as_float(hi & 0xFFFF0000u);
    lo = pack_bf2(f0 - h0, f1 - h1);
}

DEV_INLINE void mma_bf16(float* c, unsigned a0, unsigned a1, unsigned a2, unsigned a3,
                         unsigned b0, unsigned b1) {
    asm volatile(
        "mma.sync.aligned.m16n8k16.row.col.f32.bf16.bf16.f32 "
        "{%0,%1,%2,%3}, {%4,%5,%6,%7}, {%8,%9}, {%0,%1,%2,%3};\n"
        : "+f"(c[0]), "+f"(c[1]), "+f"(c[2]), "+f"(c[3])
        : "r"(a0), "r"(a1), "r"(a2), "r"(a3), "r"(b0), "r"(b1));
}

// ---------------- tensor-core GEMM (3xBF16 split) — EXACT R8/282.7us code ---
// C[m,n] = sum_k A[m,k] * B'[k,n]; B' = B[n,k] if b_nk else B[k,n].
// 64x64 tile, ktile 32, 256 threads (8 warps, 2x4 layout, warp tile 32x16).
constexpr int SMP2 = 68;

__global__ __launch_bounds__(256) void gemm_tc(
    const float* __restrict__ A, int lda, long long sA1, long long sA2,
    const float* __restrict__ B, int ldb, long long sB1, long long sB2,
    float* __restrict__ C, int ldc, long long sC1, long long sC2,
    int M, int Nd, int K, int HH,
    const float* __restrict__ bias, int bias_z, int b_nk) {
    __shared__ uint2 As[16][SMP2];
    __shared__ uint2 Bs[16][SMP2];
    int z = blockIdx.z, z1 = z / HH, z2 = z % HH;
    A += (size_t)z1 * sA1 + (size_t)z2 * sA2;
    B += (size_t)z1 * sB1 + (size_t)z2 * sB2;
    C += (size_t)z1 * sC1 + (size_t)z2 * sC2;
    int tid = threadIdx.x;
    int m0 = blockIdx.y * 64, n0 = blockIdx.x * 64;
    int lane = tid & 31, wid = tid >> 5;
    int wm = (wid >> 2) * 32, wn = (wid & 3) * 16;
    int tg = lane & 3, gp = lane >> 2;
    float acc[2][2][4] = {};
    const float* Ag = A + (size_t)m0 * lda;
    const float* Bg_nt = B + (size_t)n0 * ldb;

    float4 pa[2], pb[2];

    auto loadA = [&](int k0) {
#pragma unroll
        for (int it = 0; it < 2; it++) {
            int idx = tid + it * 256;
            int r = idx >> 3, c4 = idx & 7;
            pa[it] = *reinterpret_cast<const float4*>(Ag + (size_t)r * lda + k0 + c4 * 4);
        }
    };
    auto storeA = [&]() {
#pragma unroll
        for (int it = 0; it < 2; it++) {
            int idx = tid + it * 256;
            int r = idx >> 3, kp = (idx & 7) * 2;
            unsigned h0, l0, h1, l1;
            split2(pa[it].x, pa[it].y, h0, l0);
            split2(pa[it].z, pa[it].w, h1, l1);
            As[kp][r] = make_uint2(h0, l0);
            As[kp + 1][r] = make_uint2(h1, l1);
        }
    };
    auto loadB = [&](int k0) {
        if (b_nk) {
#pragma unroll
            for (int it = 0; it < 2; it++) {
                int idx = tid + it * 256;
                int r = idx >> 3, c4 = idx & 7;
                pb[it] = *reinterpret_cast<const float4*>(Bg_nt + (size_t)r * ldb + k0 + c4 * 4);
            }
        } else {
            int kp = tid >> 4, nc = (tid & 15) * 4;
            pb[0] = *reinterpret_cast<const float4*>(B + (size_t)(k0 + 2 * kp) * ldb + n0 + nc);
            pb[1] = *reinterpret_cast<const float4*>(B + (size_t)(k0 + 2 * kp + 1) * ldb + n0 + nc);
        }
    };
    auto storeB = [&]() {
        if (b_nk) {
#pragma unroll
            for (int it = 0; it < 2; it++) {
                int idx = tid + it * 256;
                int r = idx >> 3, kp = (idx & 7) * 2;
                unsigned h0, l0, h1, l1;
                split2(pb[it].x, pb[it].y, h0, l0);
                split2(pb[it].z, pb[it].w, h1, l1);
                Bs[kp][r] = make_uint2(h0, l0);
                Bs[kp + 1][r] = make_uint2(h1, l1);
            }
        } else {
            int kp = tid >> 4, nc = (tid & 15) * 4;
            float fe[4] = {pb[0].x, pb[0].y, pb[0].z, pb[0].w};
            float fo[4] = {pb[1].x, pb[1].y, pb[1].z, pb[1].w};
#pragma unroll
            for (int j = 0; j < 4; j++) {
                unsigned h, l;
                split2(fe[j], fo[j], h, l);
                Bs[kp][nc + j] = make_uint2(h, l);
            }
        }
    };

    loadA(0);
    loadB(0);
    for (int k0 = 0; k0 < K; k0 += 32) {
        storeA();
        storeB();
        __syncthreads();
        if (k0 + 32 < K) { loadA(k0 + 32); loadB(k0 + 32); }
#pragma unroll
        for (int ks = 0; ks < 16; ks += 8) {
            uint2 af[2][4], bf[2][2];
#pragma unroll
            for (int mt = 0; mt < 2; mt++) {
                int m = wm + mt * 16 + gp;
                af[mt][0] = As[ks + tg][m];     af[mt][1] = As[ks + tg][m + 8];
                af[mt][2] = As[ks + tg + 4][m]; af[mt][3] = As[ks + tg + 4][m + 8];
            }
#pragma unroll
            for (int nt = 0; nt < 2; nt++) {
                int n = wn + nt * 8 + gp;
                bf[nt][0] = Bs[ks + tg][n];
                bf[nt][1] = Bs[ks + tg + 4][n];
            }
            // hi*hi
#pragma unroll
            for (int nt = 0; nt < 2; nt++)
#pragma unroll
                for (int mt = 0; mt < 2; mt++)
                    mma_bf16(acc[mt][nt], af[mt][0].x, af[mt][1].x, af[mt][2].x, af[mt][3].x,
                             bf[nt][0].x, bf[nt][1].x);
            // lo*hi
#pragma unroll
            for (int nt = 0; nt < 2; nt++)
#pragma unroll
                for (int mt = 0; mt < 2; mt++)
                    mma_bf16(acc[mt][nt], af[mt][0].y, af[mt][1].y, af[mt][2].y, af[mt][3].y,
                             bf[nt][0].x, bf[nt][1].x);
            // hi*lo
#pragma unroll
            for (int nt = 0; nt < 2; nt++)
#pragma unroll
                for (int mt = 0; mt < 2; mt++)
                    mma_bf16(acc[mt][nt], af[mt][0].x, af[mt][1].x, af[mt][2].x, af[mt][3].x,
                             bf[nt][0].y, bf[nt][1].y);
        }
        __syncthreads();
    }
    bool useb = (bias != nullptr) && (z2 < bias_z);
#pragma unroll
    for (int mt = 0; mt < 2; mt++) {
        int r = m0 + wm + mt * 16 + gp;
#pragma unroll
        for (int nt = 0; nt < 2; nt++) {
            int ncol = n0 + wn + nt * 8 + tg * 2;
            float b0v = useb ? bias[ncol] : 0.f;
            float b1v = useb ? bias[ncol + 1] : 0.f;
            C[(size_t)r * ldc + ncol]           = acc[mt][nt][0] + b0v;
            C[(size_t)r * ldc + ncol + 1]       = acc[mt][nt][1] + b1v;
            C[(size_t)(r + 8) * ldc + ncol]     = acc[mt][nt][2] + b0v;
            C[(size_t)(r + 8) * ldc + ncol + 1] = acc[mt][nt][3] + b1v;
        }
    }
}

// ---------------- CLONE: t2 GEMM with fused bn1-affine+relu on A ------------
// Separate kernel so the hot gemm_tc above compiles untouched.
__global__ __launch_bounds__(256) void gemm_tc_bn(
    const float* __restrict__ A, int lda,
    const float* __restrict__ B, int ldb,
    float* __restrict__ C, int ldc,
    int M, int Nd, int K,
    const float* __restrict__ a_sc, const float* __restrict__ a_sh) {
    __shared__ uint2 As[16][SMP2];
    __shared__ uint2 Bs[16][SMP2];
    int tid = threadIdx.x;
    int m0 = blockIdx.y * 64, n0 = blockIdx.x * 64;
    int lane = tid & 31, wid = tid >> 5;
    int wm = (wid >> 2) * 32, wn = (wid & 3) * 16;
    int tg = lane & 3, gp = lane >> 2;
    float acc[2][2][4] = {};
    const float* Ag = A + (size_t)m0 * lda;
    const float* Bg = B + (size_t)n0 * ldb;

    float4 pa[2], pb[2];

    auto loadA = [&](int k0) {
#pragma unroll
        for (int it = 0; it < 2; it++) {
            int idx = tid + it * 256;
            int r = idx >> 3, c4 = idx & 7;
            pa[it] = *reinterpret_cast<const float4*>(Ag + (size_t)r * lda + k0 + c4 * 4);
        }
    };
    auto storeA = [&](int k0) {
#pragma unroll
        for (int it = 0; it < 2; it++) {
            int idx = tid + it * 256;
            int r = idx >> 3, kp = (idx & 7) * 2;
            int k = k0 + (idx & 7) * 4;
            float4 s4 = *reinterpret_cast<const float4*>(a_sc + k);
            float4 h4 = *reinterpret_cast<const float4*>(a_sh + k);
            float v0 = fmaxf(pa[it].x * s4.x + h4.x, 0.f);
            float v1 = fmaxf(pa[it].y * s4.y + h4.y, 0.f);
            float v2 = fmaxf(pa[it].z * s4.z + h4.z, 0.f);
            float v3 = fmaxf(pa[it].w * s4.w + h4.w, 0.f);
            unsigned h0, l0, h1, l1;
            split2(v0, v1, h0, l0);
            split2(v2, v3, h1, l1);
            As[kp][r] = make_uint2(h0, l0);
            As[kp + 1][r] = make_uint2(h1, l1);
        }
    };
    auto loadB = [&](int k0) {
#pragma unroll
        for (int it = 0; it < 2; it++) {
            int idx = tid + it * 256;
            int r = idx >> 3, c4 = idx & 7;
            pb[it] = *reinterpret_cast<const float4*>(Bg + (size_t)r * ldb + k0 + c4 * 4);
        }
    };
    auto storeB = [&]() {
#pragma unroll
        for (int it = 0; it < 2; it++) {
            int idx = tid + it * 256;
            int r = idx >> 3, kp = (idx & 7) * 2;
            unsigned h0, l0, h1, l1;
            split2(pb[it].x, pb[it].y, h0, l0);
            split2(pb[it].z, pb[it].w, h1, l1);
            Bs[kp][r] = make_uint2(h0, l0);
            Bs[kp + 1][r] = make_uint2(h1, l1);
        }
    };

    loadA(0);
    loadB(0);
    for (int k0 = 0; k0 < K; k0 += 32) {
        storeA(k0);
        storeB();
        __syncthreads();
        if (k0 + 32 < K) { loadA(k0 + 32); loadB(k0 + 32); }
#pragma unroll
        for (int ks = 0; ks < 16; ks += 8) {
            uint2 af[2][4], bf[2][2];
#pragma unroll
            for (int mt = 0; mt < 2; mt++) {
                int m = wm + mt * 16 + gp;
                af[mt][0] = As[ks + tg][m];     af[mt][1] = As[ks + tg][m + 8];
                af[mt][2] = As[ks + tg + 4][m]; af[mt][3] = As[ks + tg + 4][m + 8];
            }
#pragma unroll
            for (int nt = 0; nt < 2; nt++) {
                int n = wn + nt * 8 + gp;
                bf[nt][0] = Bs[ks + tg][n];
                bf[nt][1] = Bs[ks + tg + 4][n];
            }
#pragma unroll
            for (int nt = 0; nt < 2; nt++)
#pragma unroll
                for (int mt = 0; mt < 2; mt++)
                    mma_bf16(acc[mt][nt], af[mt][0].x, af[mt][1].x, af[mt][2].x, af[mt][3].x,
                             bf[nt][0].x, bf[nt][1].x);
#pragma unroll
            for (int nt = 0; nt < 2; nt++)
#pragma unroll
                for (int mt = 0; mt < 2; mt++)
                    mma_bf16(acc[mt][nt], af[mt][0].y, af[mt][1].y, af[mt][2].y, af[mt][3].y,
                             bf[nt][0].x, bf[nt][1].x);
#pragma unroll
            for (int nt = 0; nt < 2; nt++)
#pragma unroll
                for (int mt = 0; mt < 2; mt++)
                    mma_bf16(acc[mt][nt], af[mt][0].x, af[mt][1].x, af[mt][2].x, af[mt][3].x,
                             bf[nt][0].y, bf[nt][1].y);
        }
        __syncthreads();
    }
#pragma unroll
    for (int mt = 0; mt < 2; mt++) {
        int r = m0 + wm + mt * 16 + gp;
#pragma unroll
        for (int nt = 0; nt < 2; nt++) {
            int ncol = n0 + wn + nt * 8 + tg * 2;
            C[(size_t)r * ldc + ncol]           = acc[mt][nt][0];
            C[(size_t)r * ldc + ncol + 1]       = acc[mt][nt][1];
            C[(size_t)(r + 8) * ldc + ncol]     = acc[mt][nt][2];
            C[(size_t)(r + 8) * ldc + ncol + 1] = acc[mt][nt][3];
        }
    }
}

// ---------------- attention scores s_i, s_j (warp-per-(head,half)) ----------
__global__ void si_sj2(const float* __restrict__ hp, const float* __restrict__ attw,
                       float* __restrict__ si, float* __restrict__ sj) {
    int bn = blockIdx.x;
    int b = bn >> 9, n = bn & 511;
    int t = threadIdx.x, w = t >> 5, l = t & 31;
    int h = w >> 1, part = w & 1;
    const float* row = hp + (size_t)bn * cF + h * cDH;
    const float* aw = attw + h * 2 * cDH + part * cDH;
    float s = 0.f;
#pragma unroll
    for (int q = 0; q < 8; q++) {
        int d = q * 32 + l;
        s += row[d] * aw[d];
    }
#pragma unroll
    for (int o = 16; o; o >>= 1) s += __shfl_down_sync(0xffffffffu, s, o);
    if (l == 0) {
        float* dst = part ? sj : si;
        dst[((size_t)(b * cH + h)) * cN + n] = s;
    }
}

// ---------------- per-row attention softmax ----------------
__global__ void attn_softmax(const float* __restrict__ si, const float* __restrict__ sj,
                             float* __restrict__ alpha) {
    int id = blockIdx.x;
    int i = id & 511, bh = id >> 9;
    float s_i = si[(size_t)bh * cN + i];
    const float* sjr = sj + (size_t)bh * cN;
    int t = threadIdx.x;
    float x0 = s_i + sjr[t];
    float x1 = s_i + sjr[t + 256];
    float e0 = x0 >= 0.f ? x0 : 0.2f * x0;
    float e1 = x1 >= 0.f ? x1 : 0.2f * x1;
    float m = blockReduceF(fmaxf(e0, e1), MaxOp(), -1e30f);
    float p0 = expf(e0 - m), p1 = expf(e1 - m);
    float s = blockReduceF(p0 + p1, SumOp(), 0.f);
    float inv = 1.f / s;
    float* arow = alpha + (size_t)id * cN;
    arow[t] = p0 * inv;
    arow[t + 256] = p1 * inv;
}

// ---------------- edge MLP + global-max epilogue ----------------
__global__ void edge_kernel(const float* __restrict__ pi, const float* __restrict__ pj,
                            const float* __restrict__ w2, const float* __restrict__ b2,
                            float* __restrict__ es) {
    __shared__ float pis[32][65];
    __shared__ float pjs[32][65];
    __shared__ float w2s[32];
    int b = blockIdx.z;
    int i0 = blockIdx.y * 64, j0 = blockIdx.x * 64;
    int tid = threadIdx.x;
    int tx = tid & 15, ty = tid >> 4;
    float acc[4][4] = {};
    for (int a0 = 0; a0 < cAH; a0 += 32) {
        for (int idx = tid; idx < 64 * 32; idx += 256) {
            int a = idx & 31, r = idx >> 5;
            pis[a][r] = pi[((size_t)(b * cN + i0 + r)) * cAH + a0 + a];
            pjs[a][r] = pj[((size_t)(b * cN + j0 + r)) * cAH + a0 + a];
        }
        if (tid < 32) w2s[tid] = w2[a0 + tid];
        __syncthreads();
#pragma unroll 8
        for (int a = 0; a < 32; a++) {
            float w = w2s[a];
            float pv[4], qv[4];
#pragma unroll
            for (int u = 0; u < 4; u++) pv[u] = pis[a][ty + 16 * u];
#pragma unroll
            for (int v = 0; v < 4; v++) qv[v] = pjs[a][tx + 16 * v];
#pragma unroll
            for (int u = 0; u < 4; u++)
#pragma unroll
                for (int v = 0; v < 4; v++)
                    acc[u][v] += fmaxf(pv[u] + qv[v], 0.f) * w;
        }
        __syncthreads();
    }
    float bb = b2[0];
    float lmax = -1e30f;
#pragma unroll
    for (int u = 0; u < 4; u++)
#pragma unroll
        for (int v = 0; v < 4; v++) {
            float val = acc[u][v] + bb;
            es[((size_t)b * cN + i0 + ty + 16 * u) * cN + j0 + tx + 16 * v] = val;
            lmax = fmaxf(lmax, val);
        }
    lmax = blockReduceF(lmax, MaxOp(), -1e30f);
    if (tid == 0) atomicMax(&g_maxkey[b], okey(lmax));
}

// ---------------- exact radix select: 3 passes (11/11/10 bits) --------------
__global__ void sel_init() {
    int t = blockIdx.x * blockDim.x + threadIdx.x;
    if (t < cB * 2048) g_hist2[t] = 0;
    if (t < cB) { g_prefix[t] = 0; g_rank[t] = RANK_SEL; g_maxkey[t] = 0; }
}

__global__ void sel_hist_g(const float* __restrict__ es, int pass) {
    int b = blockIdx.y;
    __shared__ unsigned hist[2048];
    for (int i = threadIdx.x; i < 2048; i += 256) hist[i] = 0;
    __syncthreads();
    unsigned prefix = g_prefix[b];
    const float* data = es + (size_t)b * NN;
    int per = NN / gridDim.x;
    int base = blockIdx.x * per;
    for (int i = threadIdx.x; i < per; i += 256) {
        unsigned u = okey(data[base + i]);
        int bin = -1;
        if (pass == 0) bin = (int)(u >> 21);
        else if (pass == 1) { if ((u >> 21) == (prefix >> 21)) bin = (int)((u >> 10) & 0x7FFu); }
        else { if ((u >> 10) == (prefix >> 10)) bin = (int)(u & 0x3FFu); }
        unsigned mask = __match_any_sync(0xffffffffu, bin);
        if (bin >= 0 && ((threadIdx.x & 31) == (__ffs(mask) - 1)))
            atomicAdd(&hist[bin], (unsigned)__popc(mask));
    }
    __syncthreads();
    for (int i = threadIdx.x; i < 2048; i += 256)
        if (hist[i]) atomicAdd(&g_hist2[b * 2048 + i], hist[i]);
}

__global__ void sel_step_g(float* __restrict__ red, int pass) {
    int b = blockIdx.x;
    int t = threadIdx.x;  // 256
    unsigned* hist = g_hist2 + (size_t)b * 2048;
    unsigned loc[8];
    unsigned psum = 0;
#pragma unroll
    for (int q = 0; q < 8; q++) { loc[q] = hist[t * 8 + q]; psum += loc[q]; }
    __shared__ unsigned sh[256];
    __shared__ int s_sel;
    __shared__ unsigned s_cum;
    sh[t] = psum;
    __syncthreads();
    if (t == 0) {
        int r = g_rank[b];
        unsigned cum = 0;
        int ti = 0;
        for (; ti < 255; ti++) {
            if (cum + sh[ti] > (unsigned)r) break;
            cum += sh[ti];
        }
        s_sel = ti;
        s_cum = cum;
    }
    __syncthreads();
    if (t == s_sel) {
        int r = g_rank[b];
        unsigned cum = s_cum;
        int bin = t * 8;
#pragma unroll
        for (int q = 0; q < 8; q++) {
            if (cum + loc[q] > (unsigned)r) { bin = t * 8 + q; break; }
            cum += loc[q];
        }
        g_rank[b] = r - (int)cum;
        unsigned p;
        if (pass == 0) p = (unsigned)bin << 21;
        else if (pass == 1) p = g_prefix[b] | ((unsigned)bin << 10);
        else p = g_prefix[b] | (unsigned)bin;
        g_prefix[b] = p;
        if (pass == 2) red[b * 8 + 2] = __uint_as_float(p);
    }
    __syncthreads();
    for (int i = t; i < 2048; i += 256) hist[i] = 0;  // re-zero for replay
}

// ---------------- kept-sum + full-sum of exp(2(e-m)) in one pass ------------
__global__ void csum2_kernel(const float* __restrict__ es, const float* __restrict__ red,
                             float* __restrict__ part) {
    int b = blockIdx.y, seg = blockIdx.x;
    unsigned thr = __float_as_uint(red[b * 8 + 2]);
    float m = okey_dec(g_maxkey[b]);
    const float* p = es + (size_t)b * NN + seg * 2048;
    float sk = 0.f, sz = 0.f;
    for (int i = threadIdx.x; i < 2048; i += 256) {
        float v = p[i];
        float e = expf(2.f * (v - m));
        sz += e;
        if (okey(v) >= thr) sk += e;
    }
    sk = blockReduceF(sk, SumOp(), 0.f);
    sz = blockReduceF(sz, SumOp(), 0.f);
    if (threadIdx.x == 0) {
        part[b * 256 + seg] = sk;
        part[b * 256 + 128 + seg] = sz;
    }
}

__global__ void reduce2_kernel(const float* __restrict__ part, float* __restrict__ red) {
    int b = blockIdx.x;
    float v1 = part[b * 256 + threadIdx.x];
    float v2 = part[b * 256 + 128 + threadIdx.x];
    v1 = blockReduceF(v1, SumOp(), 0.f);
    v2 = blockReduceF(v2, SumOp(), 0.f);
    if (threadIdx.x == 0) {
        red[b * 8 + 3] = v1;  // S_kept
        red[b * 8 + 4] = v2;  // Z
    }
}

__global__ void adj_write(const float* __restrict__ es, const float* __restrict__ red,
                          float* __restrict__ adj) {
    size_t i = (size_t)blockIdx.x * blockDim.x + threadIdx.x;
    int b = (int)(i / NN);
    unsigned thr = __float_as_uint(red[b * 8 + 2]);
    float m = okey_dec(g_maxkey[b]);
    float inv = 1.f / (red[b * 8 + 3] + red[b * 8 + 4] * 1e-12f);
    float v = es[i];
    adj[i] = (okey(v) >= thr) ? expf(2.f * (v - m)) * inv : 0.f;
}

// ---------------- batchnorm ----------------
__global__ void bn_stats(const float* __restrict__ h, int C, float* __restrict__ stats) {
    int c = blockIdx.x;
    double s = 0.0, s2 = 0.0;
    for (int r = threadIdx.x; r < cB * cN; r += blockDim.x) {
        double v = (double)h[(size_t)r * C + c];
        s += v;
        s2 += v * v;
    }
    s = blockReduceD(s);
    s2 = blockReduceD(s2);
    if (threadIdx.x == 0) {
        double m = s / (cB * cN);
        double var = s2 / (cB * cN) - m * m;
        stats[2 * c] = (float)m;
        stats[2 * c + 1] = (float)rsqrt(var + 1e-5);
    }
}

// fold bn stats + gamma/beta into per-channel scale/shift
__global__ void bn_prep(const float* __restrict__ stats, const float* __restrict__ ga,
                        const float* __restrict__ be, float* __restrict__ sc,
                        float* __restrict__ sh, int C) {
    int c = blockIdx.x * blockDim.x + threadIdx.x;
    if (c < C) {
        float s = stats[2 * c + 1] * ga[c];
        sc[c] = s;
        sh[c] = be[c] - stats[2 * c] * s;
    }
}

// ---------------- final ----------------
__global__ void final_kernel(const float* __restrict__ g2, const float* __restrict__ stats,
                             const float* __restrict__ ga, const float* __restrict__ be,
                             const float* __restrict__ clsw, const float* __restrict__ clsb,
                             float* __restrict__ out) {
    int b = blockIdx.x, c = threadIdx.x;
    float m = stats[2 * c], is = stats[2 * c + 1], gg = ga[c], bb = be[c];
    float s = 0.f;
    for (int n = 0; n < cN; n++) {
        float v = g2[((size_t)(b * cN + n)) * cOUT + c];
        v = (v - m) * is * gg + bb;
        s += fmaxf(v, 0.f);
    }
    __shared__ float feat[cOUT];
    feat[c] = s * (1.f / cN);
    __syncthreads();
    if (c < cNC) {
        float o = clsb[c];
        for (int q = 0; q < cOUT; q++) o += feat[q] * clsw[c * cOUT + q];
        out[b * cNC + c] = o;
    }
}

// ---------------- launch ----------------
extern "C" void kernel_launch(void* const* d_in, const int* in_sizes, int n_in,
                              void* d_out, int out_size) {
    const float* x      = (const float*)d_in[0];
    const float* Wg     = (const float*)d_in[1];
    const float* attn_w = (const float*)d_in[2];
    const float* W1     = (const float*)d_in[3];
    const float* b1     = (const float*)d_in[4];
    const float* w2     = (const float*)d_in[5];
    const float* b2     = (const float*)d_in[6];
    const float* gc1_w  = (const float*)d_in[7];
    const float* gc1_b  = (const float*)d_in[8];
    const float* bn1g   = (const float*)d_in[9];
    const float* bn1b   = (const float*)d_in[10];
    const float* gc2_w  = (const float*)d_in[11];
    const float* gc2_b  = (const float*)d_in[12];
    const float* bn2g   = (const float*)d_in[13];
    const float* bn2b   = (const float*)d_in[14];
    const float* clsw   = (const float*)d_in[15];
    const float* clsb   = (const float*)d_in[16];

    float* buf = nullptr;
    cudaGetSymbolAddress((void**)&buf, g_buf);
    float* hp    = buf + OFF_HP;
    float* alpha = buf + OFF_ALPHA;
    float* nf    = buf + OFF_NF;
    float* pi    = buf + OFF_PI;
    float* pj    = buf + OFF_PJ;
    float* es    = buf + OFF_ES;
    float* adj   = buf + OFF_ADJ;
    float* t1    = buf + OFF_H1;
    float* g1    = buf + OFF_G1;
    float* t2    = buf + OFF_H2;
    float* g2    = buf + OFF_G2;
    float* si    = buf + OFF_SI;
    float* sj    = buf + OFF_SJ;
    float* part  = buf + OFF_PART;
    float* red   = buf + OFF_RED;
    float* bn1s  = buf + OFF_BN1;
    float* bn2s  = buf + OFF_BN2;
    float* bnsc  = buf + OFF_BNP;
    float* bnsh  = buf + OFF_BNP + cHID;

    typedef long long ll;

    // 0) init select state (before edge_kernel's atomicMax)
    sel_init<<<16, 256>>>();
    // 1) hp = x @ Wg^T
    gemm_tc<<<dim3(cF / 64, (cB * cN) / 64, 1), 256>>>(
        x, cF, 0, 0, Wg, cF, 0, 0, hp, cF, 0, 0,
        cB * cN, cF, cF, 1, nullptr, 0, 1);
    // 2) s_i, s_j
    si_sj2<<<cB * cN, 256>>>(hp, attn_w, si, sj);
    // 3) attention softmax
    attn_softmax<<<cB * cH * cN, 256>>>(si, sj, alpha);
    // 4) node_feats = alpha @ hp (batched b,h)
    gemm_tc<<<dim3(cDH / 64, cN / 64, cB * cH), 256>>>(
        alpha, cN, (ll)cH * NN, (ll)NN,
        hp, cF, (ll)cN * cF, (ll)cDH,
        nf, cF, (ll)cN * cF, (ll)cDH,
        cN, cDH, cN, cH, nullptr, 0, 0);
    // 5) pi/pj fused (grid.z = 2)
    gemm_tc<<<dim3(cAH / 64, (cB * cN) / 64, 2), 256>>>(
        nf, cF, 0, 0,
        W1, 2 * cF, 0, (ll)cF,
        pi, cAH, 0, (ll)cB * cN * cAH,
        cB * cN, cAH, cF, 2, b1, 1, 1);
    // 6) edge scores + per-batch max
    edge_kernel<<<dim3(cN / 64, cN / 64, cB), 256>>>(pi, pj, w2, b2, es);
    // 7) exact order statistic: 3 radix passes (11/11/10 bits, smem hist)
    for (int p = 0; p < 3; p++) {
        sel_hist_g<<<dim3(64, cB), 256>>>(es, p);
        sel_step_g<<<cB, 256>>>(red, p);
    }
    // 8) kept-sum + Z; adjacency write
    csum2_kernel<<<dim3(128, cB), 256>>>(es, red, part);
    reduce2_kernel<<<cB, 128>>>(part, red);
    adj_write<<<(cB * NN) / 256, 256>>>(es, red, adj);
    // 9) stage 1 (reassociated): t1 = nf @ gc1_w^T ; g1 = adj @ t1 + gc1_b
    gemm_tc<<<dim3(cHID / 64, (cB * cN) / 64, 1), 256>>>(
        nf, cF, 0, 0, gc1_w, cF, 0, 0, t1, cHID, 0, 0,
        cB * cN, cHID, cF, 1, nullptr, 0, 1);
    gemm_tc<<<dim3(cHID / 64, cN / 64, cB), 256>>>(
        adj, cN, (ll)NN, 0,
        t1, cHID, (ll)cN * cHID, 0,
        g1, cHID, (ll)cN * cHID, 0,
        cN, cHID, cN, 1, gc1_b, 1, 0);
    bn_stats<<<cHID, 256>>>(g1, cHID, bn1s);
    bn_prep<<<2, 256>>>(bn1s, bn1g, bn1b, bnsc, bnsh, cHID);
    // 10) stage 2 (reassociated): t2 = bnrelu(g1) @ gc2_w^T via CLONE kernel,
    //     then g2 = adj @ t2 + gc2_b via the untouched gemm_tc
    gemm_tc_bn<<<dim3(cOUT / 64, (cB * cN) / 64), 256>>>(
        g1, cHID, gc2_w, cHID, t2, cOUT,
        cB * cN, cOUT, cHID, bnsc, bnsh);
    gemm_tc<<<dim3(cOUT / 64, cN / 64, cB), 256>>>(
        adj, cN, (ll)NN, 0,
        t2, cOUT, (ll)cN * cOUT, 0,
        g2, cOUT, (ll)cN * cOUT, 0,
        cN, cOUT, cN, 1, gc2_b, 1, 0);
    bn_stats<<<cOUT, 256>>>(g2, cOUT, bn2s);
    // 11) final
    final_kernel<<<cB, 128>>>(g2, bn2s, bn2g, bn2b, clsw, clsb, (float*)d_out);
}

// round 15
// speedup vs baseline: 1.7855x; 1.0202x over previous
#include <cuda_runtime.h>
#include <math.h>

#define DEV_INLINE __device__ __forceinline__

// ---------------- problem constants ----------------
constexpr int cB = 2, cN = 512, cF = 1024, cH = 4, cDH = 256;
constexpr int cAH = 256, cHID = 512, cOUT = 128, cNC = 10;
constexpr int NN = cN * cN;               // 262144
constexpr int KSEL = 209715;              // int(0.8 * 512 * 512)
constexpr int RANK_SEL = NN - KSEL;       // 52429

// ---------------- scratch layout ----------------
constexpr size_t OFF_HP    = 0;
constexpr size_t OFF_ALPHA = OFF_HP    + (size_t)cB * cN * cF;
constexpr size_t OFF_NF    = OFF_ALPHA + (size_t)cB * cH * cN * cN;
constexpr size_t OFF_PI    = OFF_NF    + (size_t)cB * cN * cF;
constexpr size_t OFF_PJ    = OFF_PI    + (size_t)cB * cN * cAH;
constexpr size_t OFF_ES    = OFF_PJ    + (size_t)cB * cN * cAH;
constexpr size_t OFF_ADJ   = OFF_ES    + (size_t)cB * NN;
constexpr size_t OFF_H1    = OFF_ADJ   + (size_t)cB * NN;
constexpr size_t OFF_G1    = OFF_H1    + (size_t)cB * cN * cF;
constexpr size_t OFF_H2    = OFF_G1    + (size_t)cB * cN * cHID;
constexpr size_t OFF_G2    = OFF_H2    + (size_t)cB * cN * cHID;
constexpr size_t OFF_SI    = OFF_G2    + (size_t)cB * cN * cOUT;
constexpr size_t OFF_SJ    = OFF_SI    + (size_t)cB * cH * cN;
constexpr size_t OFF_PART  = OFF_SJ    + (size_t)cB * cH * cN;
constexpr size_t OFF_RED   = OFF_PART  + (size_t)cB * 256;
constexpr size_t OFF_BN1   = OFF_RED   + (size_t)cB * 8;
constexpr size_t OFF_BN2   = OFF_BN1   + (size_t)2 * cHID;
constexpr size_t OFF_BNP   = OFF_BN2   + (size_t)2 * cOUT;   // folded bn1 scale/shift
constexpr size_t BUF_TOTAL = OFF_BNP   + (size_t)2 * cHID;

__device__ float    g_buf[BUF_TOTAL];
__device__ unsigned g_hist2[cB * 2048];
__device__ unsigned g_prefix[cB];
__device__ int      g_rank[cB];
__device__ unsigned g_maxkey[cB];

// ---------------- order-preserving float<->key transform ----------------
DEV_INLINE unsigned okey(float f) {
    int u = __float_as_int(f);
    return (unsigned)(u ^ ((u >> 31) | 0x80000000));
}
DEV_INLINE float okey_dec(unsigned k) {
    unsigned u = (k & 0x80000000u) ? (k ^ 0x80000000u) : ~k;
    return __uint_as_float(u);
}

// ---------------- reductions ----------------
struct SumOp { DEV_INLINE float operator()(float a, float b) const { return a + b; } };
struct MaxOp { DEV_INLINE float operator()(float a, float b) const { return fmaxf(a, b); } };

template <typename Op>
DEV_INLINE float blockReduceF(float v, Op op, float init) {
    __shared__ float sh[32];
    __syncthreads();
    int lane = threadIdx.x & 31, w = threadIdx.x >> 5;
#pragma unroll
    for (int o = 16; o; o >>= 1) v = op(v, __shfl_down_sync(0xffffffffu, v, o));
    if (lane == 0) sh[w] = v;
    __syncthreads();
    int nw = (blockDim.x + 31) >> 5;
    v = (threadIdx.x < nw) ? sh[threadIdx.x] : init;
    if (w == 0) {
#pragma unroll
        for (int o = 16; o; o >>= 1) v = op(v, __shfl_down_sync(0xffffffffu, v, o));
        if (lane == 0) sh[0] = v;
    }
    __syncthreads();
    return sh[0];
}

DEV_INLINE double blockReduceD(double v) {
    __shared__ double shd[32];
    __syncthreads();
    int lane = threadIdx.x & 31, w = threadIdx.x >> 5;
#pragma unroll
    for (int o = 16; o; o >>= 1) v += __shfl_down_sync(0xffffffffu, v, o);
    if (lane == 0) shd[w] = v;
    __syncthreads();
    int nw = (blockDim.x + 31) >> 5;
    v = (threadIdx.x < nw) ? shd[threadIdx.x] : 0.0;
    if (w == 0) {
#pragma unroll
        for (int o = 16; o; o >>= 1) v += __shfl_down_sync(0xffffffffu, v, o);
        if (lane == 0) shd[0] = v;
    }
    __syncthreads();
    return shd[0];
}

// ---------------- bf16 split helpers ----------------
DEV_INLINE unsigned pack_bf2(float f_even, float f_odd) {
    unsigned r;
    asm("cvt.rn.bf16x2.f32 %0, %1, %2;" : "=r"(r) : "f"(f_odd), "f"(f_even));
    return r;
}
DEV_INLINE void split2(float f0, float f1, unsigned& hi, unsigned& lo) {
    hi = pack_bf2(f0, f1);
    float h0 = __uint_as_float(hi << 16);
    float h1 = __uint_as_float(hi & 0xFFFF0000u);
    lo = pack_bf2(f0 - h0, f1 - h1);
}

DEV_INLINE void mma_bf16(float* c, unsigned a0, unsigned a1, unsigned a2, unsigned a3,
                         unsigned b0, unsigned b1) {
    asm volatile(
        "mma.sync.aligned.m16n8k16.row.col.f32.bf16.bf16.f32 "
        "{%0,%1,%2,%3}, {%4,%5,%6,%7}, {%8,%9}, {%0,%1,%2,%3};\n"
        : "+f"(c[0]), "+f"(c[1]), "+f"(c[2]), "+f"(c[3])
        : "r"(a0), "r"(a1), "r"(a2), "r"(a3), "r"(b0), "r"(b1));
}

// ---------------- tensor-core GEMM (3xBF16 split) — EXACT R8/282.7us code ---
// C[m,n] = sum_k A[m,k] * B'[k,n]; B' = B[n,k] if b_nk else B[k,n].
// 64x64 tile, ktile 32, 256 threads (8 warps, 2x4 layout, warp tile 32x16).
constexpr int SMP2 = 68;

__global__ __launch_bounds__(256) void gemm_tc(
    const float* __restrict__ A, int lda, long long sA1, long long sA2,
    const float* __restrict__ B, int ldb, long long sB1, long long sB2,
    float* __restrict__ C, int ldc, long long sC1, long long sC2,
    int M, int Nd, int K, int HH,
    const float* __restrict__ bias, int bias_z, int b_nk) {
    __shared__ uint2 As[16][SMP2];
    __shared__ uint2 Bs[16][SMP2];
    int z = blockIdx.z, z1 = z / HH, z2 = z % HH;
    A += (size_t)z1 * sA1 + (size_t)z2 * sA2;
    B += (size_t)z1 * sB1 + (size_t)z2 * sB2;
    C += (size_t)z1 * sC1 + (size_t)z2 * sC2;
    int tid = threadIdx.x;
    int m0 = blockIdx.y * 64, n0 = blockIdx.x * 64;
    int lane = tid & 31, wid = tid >> 5;
    int wm = (wid >> 2) * 32, wn = (wid & 3) * 16;
    int tg = lane & 3, gp = lane >> 2;
    float acc[2][2][4] = {};
    const float* Ag = A + (size_t)m0 * lda;
    const float* Bg_nt = B + (size_t)n0 * ldb;

    float4 pa[2], pb[2];

    auto loadA = [&](int k0) {
#pragma unroll
        for (int it = 0; it < 2; it++) {
            int idx = tid + it * 256;
            int r = idx >> 3, c4 = idx & 7;
            pa[it] = *reinterpret_cast<const float4*>(Ag + (size_t)r * lda + k0 + c4 * 4);
        }
    };
    auto storeA = [&]() {
#pragma unroll
        for (int it = 0; it < 2; it++) {
            int idx = tid + it * 256;
            int r = idx >> 3, kp = (idx & 7) * 2;
            unsigned h0, l0, h1, l1;
            split2(pa[it].x, pa[it].y, h0, l0);
            split2(pa[it].z, pa[it].w, h1, l1);
            As[kp][r] = make_uint2(h0, l0);
            As[kp + 1][r] = make_uint2(h1, l1);
        }
    };
    auto loadB = [&](int k0) {
        if (b_nk) {
#pragma unroll
            for (int it = 0; it < 2; it++) {
                int idx = tid + it * 256;
                int r = idx >> 3, c4 = idx & 7;
                pb[it] = *reinterpret_cast<const float4*>(Bg_nt + (size_t)r * ldb + k0 + c4 * 4);
            }
        } else {
            int kp = tid >> 4, nc = (tid & 15) * 4;
            pb[0] = *reinterpret_cast<const float4*>(B + (size_t)(k0 + 2 * kp) * ldb + n0 + nc);
            pb[1] = *reinterpret_cast<const float4*>(B + (size_t)(k0 + 2 * kp + 1) * ldb + n0 + nc);
        }
    };
    auto storeB = [&]() {
        if (b_nk) {
#pragma unroll
            for (int it = 0; it < 2; it++) {
                int idx = tid + it * 256;
                int r = idx >> 3, kp = (idx & 7) * 2;
                unsigned h0, l0, h1, l1;
                split2(pb[it].x, pb[it].y, h0, l0);
                split2(pb[it].z, pb[it].w, h1, l1);
                Bs[kp][r] = make_uint2(h0, l0);
                Bs[kp + 1][r] = make_uint2(h1, l1);
            }
        } else {
            int kp = tid >> 4, nc = (tid & 15) * 4;
            float fe[4] = {pb[0].x, pb[0].y, pb[0].z, pb[0].w};
            float fo[4] = {pb[1].x, pb[1].y, pb[1].z, pb[1].w};
#pragma unroll
            for (int j = 0; j < 4; j++) {
                unsigned h, l;
                split2(fe[j], fo[j], h, l);
                Bs[kp][nc + j] = make_uint2(h, l);
            }
        }
    };

    loadA(0);
    loadB(0);
    for (int k0 = 0; k0 < K; k0 += 32) {
        storeA();
        storeB();
        __syncthreads();
        if (k0 + 32 < K) { loadA(k0 + 32); loadB(k0 + 32); }
#pragma unroll
        for (int ks = 0; ks < 16; ks += 8) {
            uint2 af[2][4], bf[2][2];
#pragma unroll
            for (int mt = 0; mt < 2; mt++) {
                int m = wm + mt * 16 + gp;
                af[mt][0] = As[ks + tg][m];     af[mt][1] = As[ks + tg][m + 8];
                af[mt][2] = As[ks + tg + 4][m]; af[mt][3] = As[ks + tg + 4][m + 8];
            }
#pragma unroll
            for (int nt = 0; nt < 2; nt++) {
                int n = wn + nt * 8 + gp;
                bf[nt][0] = Bs[ks + tg][n];
                bf[nt][1] = Bs[ks + tg + 4][n];
            }
            // hi*hi
#pragma unroll
            for (int nt = 0; nt < 2; nt++)
#pragma unroll
                for (int mt = 0; mt < 2; mt++)
                    mma_bf16(acc[mt][nt], af[mt][0].x, af[mt][1].x, af[mt][2].x, af[mt][3].x,
                             bf[nt][0].x, bf[nt][1].x);
            // lo*hi
#pragma unroll
            for (int nt = 0; nt < 2; nt++)
#pragma unroll
                for (int mt = 0; mt < 2; mt++)
                    mma_bf16(acc[mt][nt], af[mt][0].y, af[mt][1].y, af[mt][2].y, af[mt][3].y,
                             bf[nt][0].x, bf[nt][1].x);
            // hi*lo
#pragma unroll
            for (int nt = 0; nt < 2; nt++)
#pragma unroll
                for (int mt = 0; mt < 2; mt++)
                    mma_bf16(acc[mt][nt], af[mt][0].x, af[mt][1].x, af[mt][2].x, af[mt][3].x,
                             bf[nt][0].y, bf[nt][1].y);
        }
        __syncthreads();
    }
    bool useb = (bias != nullptr) && (z2 < bias_z);
#pragma unroll
    for (int mt = 0; mt < 2; mt++) {
        int r = m0 + wm + mt * 16 + gp;
#pragma unroll
        for (int nt = 0; nt < 2; nt++) {
            int ncol = n0 + wn + nt * 8 + tg * 2;
            float b0v = useb ? bias[ncol] : 0.f;
            float b1v = useb ? bias[ncol + 1] : 0.f;
            C[(size_t)r * ldc + ncol]           = acc[mt][nt][0] + b0v;
            C[(size_t)r * ldc + ncol + 1]       = acc[mt][nt][1] + b1v;
            C[(size_t)(r + 8) * ldc + ncol]     = acc[mt][nt][2] + b0v;
            C[(size_t)(r + 8) * ldc + ncol + 1] = acc[mt][nt][3] + b1v;
        }
    }
}

// ---------------- CLONE: t2 GEMM with fused bn1-affine+relu on A ------------
__global__ __launch_bounds__(256) void gemm_tc_bn(
    const float* __restrict__ A, int lda,
    const float* __restrict__ B, int ldb,
    float* __restrict__ C, int ldc,
    int M, int Nd, int K,
    const float* __restrict__ a_sc, const float* __restrict__ a_sh) {
    __shared__ uint2 As[16][SMP2];
    __shared__ uint2 Bs[16][SMP2];
    int tid = threadIdx.x;
    int m0 = blockIdx.y * 64, n0 = blockIdx.x * 64;
    int lane = tid & 31, wid = tid >> 5;
    int wm = (wid >> 2) * 32, wn = (wid & 3) * 16;
    int tg = lane & 3, gp = lane >> 2;
    float acc[2][2][4] = {};
    const float* Ag = A + (size_t)m0 * lda;
    const float* Bg = B + (size_t)n0 * ldb;

    float4 pa[2], pb[2];

    auto loadA = [&](int k0) {
#pragma unroll
        for (int it = 0; it < 2; it++) {
            int idx = tid + it * 256;
            int r = idx >> 3, c4 = idx & 7;
            pa[it] = *reinterpret_cast<const float4*>(Ag + (size_t)r * lda + k0 + c4 * 4);
        }
    };
    auto storeA = [&](int k0) {
#pragma unroll
        for (int it = 0; it < 2; it++) {
            int idx = tid + it * 256;
            int r = idx >> 3, kp = (idx & 7) * 2;
            int k = k0 + (idx & 7) * 4;
            float4 s4 = *reinterpret_cast<const float4*>(a_sc + k);
            float4 h4 = *reinterpret_cast<const float4*>(a_sh + k);
            float v0 = fmaxf(pa[it].x * s4.x + h4.x, 0.f);
            float v1 = fmaxf(pa[it].y * s4.y + h4.y, 0.f);
            float v2 = fmaxf(pa[it].z * s4.z + h4.z, 0.f);
            float v3 = fmaxf(pa[it].w * s4.w + h4.w, 0.f);
            unsigned h0, l0, h1, l1;
            split2(v0, v1, h0, l0);
            split2(v2, v3, h1, l1);
            As[kp][r] = make_uint2(h0, l0);
            As[kp + 1][r] = make_uint2(h1, l1);
        }
    };
    auto loadB = [&](int k0) {
#pragma unroll
        for (int it = 0; it < 2; it++) {
            int idx = tid + it * 256;
            int r = idx >> 3, c4 = idx & 7;
            pb[it] = *reinterpret_cast<const float4*>(Bg + (size_t)r * ldb + k0 + c4 * 4);
        }
    };
    auto storeB = [&]() {
#pragma unroll
        for (int it = 0; it < 2; it++) {
            int idx = tid + it * 256;
            int r = idx >> 3, kp = (idx & 7) * 2;
            unsigned h0, l0, h1, l1;
            split2(pb[it].x, pb[it].y, h0, l0);
            split2(pb[it].z, pb[it].w, h1, l1);
            Bs[kp][r] = make_uint2(h0, l0);
            Bs[kp + 1][r] = make_uint2(h1, l1);
        }
    };

    loadA(0);
    loadB(0);
    for (int k0 = 0; k0 < K; k0 += 32) {
        storeA(k0);
        storeB();
        __syncthreads();
        if (k0 + 32 < K) { loadA(k0 + 32); loadB(k0 + 32); }
#pragma unroll
        for (int ks = 0; ks < 16; ks += 8) {
            uint2 af[2][4], bf[2][2];
#pragma unroll
            for (int mt = 0; mt < 2; mt++) {
                int m = wm + mt * 16 + gp;
                af[mt][0] = As[ks + tg][m];     af[mt][1] = As[ks + tg][m + 8];
                af[mt][2] = As[ks + tg + 4][m]; af[mt][3] = As[ks + tg + 4][m + 8];
            }
#pragma unroll
            for (int nt = 0; nt < 2; nt++) {
                int n = wn + nt * 8 + gp;
                bf[nt][0] = Bs[ks + tg][n];
                bf[nt][1] = Bs[ks + tg + 4][n];
            }
#pragma unroll
            for (int nt = 0; nt < 2; nt++)
#pragma unroll
                for (int mt = 0; mt < 2; mt++)
                    mma_bf16(acc[mt][nt], af[mt][0].x, af[mt][1].x, af[mt][2].x, af[mt][3].x,
                             bf[nt][0].x, bf[nt][1].x);
#pragma unroll
            for (int nt = 0; nt < 2; nt++)
#pragma unroll
                for (int mt = 0; mt < 2; mt++)
                    mma_bf16(acc[mt][nt], af[mt][0].y, af[mt][1].y, af[mt][2].y, af[mt][3].y,
                             bf[nt][0].x, bf[nt][1].x);
#pragma unroll
            for (int nt = 0; nt < 2; nt++)
#pragma unroll
                for (int mt = 0; mt < 2; mt++)
                    mma_bf16(acc[mt][nt], af[mt][0].x, af[mt][1].x, af[mt][2].x, af[mt][3].x,
                             bf[nt][0].y, bf[nt][1].y);
        }
        __syncthreads();
    }
#pragma unroll
    for (int mt = 0; mt < 2; mt++) {
        int r = m0 + wm + mt * 16 + gp;
#pragma unroll
        for (int nt = 0; nt < 2; nt++) {
            int ncol = n0 + wn + nt * 8 + tg * 2;
            C[(size_t)r * ldc + ncol]           = acc[mt][nt][0];
            C[(size_t)r * ldc + ncol + 1]       = acc[mt][nt][1];
            C[(size_t)(r + 8) * ldc + ncol]     = acc[mt][nt][2];
            C[(size_t)(r + 8) * ldc + ncol + 1] = acc[mt][nt][3];
        }
    }
}

// ---------------- attention scores s_i, s_j (warp-per-(head,half)) ----------
__global__ void si_sj2(const float* __restrict__ hp, const float* __restrict__ attw,
                       float* __restrict__ si, float* __restrict__ sj) {
    int bn = blockIdx.x;
    int b = bn >> 9, n = bn & 511;
    int t = threadIdx.x, w = t >> 5, l = t & 31;
    int h = w >> 1, part = w & 1;
    const float* row = hp + (size_t)bn * cF + h * cDH;
    const float* aw = attw + h * 2 * cDH + part * cDH;
    float s = 0.f;
#pragma unroll
    for (int q = 0; q < 8; q++) {
        int d = q * 32 + l;
        s += row[d] * aw[d];
    }
#pragma unroll
    for (int o = 16; o; o >>= 1) s += __shfl_down_sync(0xffffffffu, s, o);
    if (l == 0) {
        float* dst = part ? sj : si;
        dst[((size_t)(b * cH + h)) * cN + n] = s;
    }
}

// ---------------- per-row attention softmax (__expf) ----------------
__global__ void attn_softmax(const float* __restrict__ si, const float* __restrict__ sj,
                             float* __restrict__ alpha) {
    int id = blockIdx.x;
    int i = id & 511, bh = id >> 9;
    float s_i = si[(size_t)bh * cN + i];
    const float* sjr = sj + (size_t)bh * cN;
    int t = threadIdx.x;
    float x0 = s_i + sjr[t];
    float x1 = s_i + sjr[t + 256];
    float e0 = x0 >= 0.f ? x0 : 0.2f * x0;
    float e1 = x1 >= 0.f ? x1 : 0.2f * x1;
    float m = blockReduceF(fmaxf(e0, e1), MaxOp(), -1e30f);
    float p0 = __expf(e0 - m), p1 = __expf(e1 - m);
    float s = blockReduceF(p0 + p1, SumOp(), 0.f);
    float inv = 1.f / s;
    float* arow = alpha + (size_t)id * cN;
    arow[t] = p0 * inv;
    arow[t + 256] = p1 * inv;
}

// ---------------- edge MLP + global-max epilogue ----------------
__global__ void edge_kernel(const float* __restrict__ pi, const float* __restrict__ pj,
                            const float* __restrict__ w2, const float* __restrict__ b2,
                            float* __restrict__ es) {
    __shared__ float pis[32][65];
    __shared__ float pjs[32][65];
    __shared__ float w2s[32];
    int b = blockIdx.z;
    int i0 = blockIdx.y * 64, j0 = blockIdx.x * 64;
    int tid = threadIdx.x;
    int tx = tid & 15, ty = tid >> 4;
    float acc[4][4] = {};
    for (int a0 = 0; a0 < cAH; a0 += 32) {
        for (int idx = tid; idx < 64 * 32; idx += 256) {
            int a = idx & 31, r = idx >> 5;
            pis[a][r] = pi[((size_t)(b * cN + i0 + r)) * cAH + a0 + a];
            pjs[a][r] = pj[((size_t)(b * cN + j0 + r)) * cAH + a0 + a];
        }
        if (tid < 32) w2s[tid] = w2[a0 + tid];
        __syncthreads();
#pragma unroll 8
        for (int a = 0; a < 32; a++) {
            float w = w2s[a];
            float pv[4], qv[4];
#pragma unroll
            for (int u = 0; u < 4; u++) pv[u] = pis[a][ty + 16 * u];
#pragma unroll
            for (int v = 0; v < 4; v++) qv[v] = pjs[a][tx + 16 * v];
#pragma unroll
            for (int u = 0; u < 4; u++)
#pragma unroll
                for (int v = 0; v < 4; v++)
                    acc[u][v] += fmaxf(pv[u] + qv[v], 0.f) * w;
        }
        __syncthreads();
    }
    float bb = b2[0];
    float lmax = -1e30f;
#pragma unroll
    for (int u = 0; u < 4; u++)
#pragma unroll
        for (int v = 0; v < 4; v++) {
            float val = acc[u][v] + bb;
            es[((size_t)b * cN + i0 + ty + 16 * u) * cN + j0 + tx + 16 * v] = val;
            lmax = fmaxf(lmax, val);
        }
    lmax = blockReduceF(lmax, MaxOp(), -1e30f);
    if (tid == 0) atomicMax(&g_maxkey[b], okey(lmax));
}

// ---------------- exact radix select: 3 passes (11/11/10 bits) --------------
__global__ void sel_init() {
    int t = blockIdx.x * blockDim.x + threadIdx.x;
    if (t < cB * 2048) g_hist2[t] = 0;
    if (t < cB) { g_prefix[t] = 0; g_rank[t] = RANK_SEL; g_maxkey[t] = 0; }
}

__global__ void sel_hist_g(const float* __restrict__ es, int pass) {
    int b = blockIdx.y;
    __shared__ unsigned hist[2048];
    for (int i = threadIdx.x; i < 2048; i += 256) hist[i] = 0;
    __syncthreads();
    unsigned prefix = g_prefix[b];
    const float4* data4 = reinterpret_cast<const float4*>(es + (size_t)b * NN);
    int per4 = (NN / 4) / gridDim.x;          // 1024 float4 per block
    int base4 = blockIdx.x * per4;
    for (int i = threadIdx.x; i < per4; i += 256) {
        float4 v4 = data4[base4 + i];
        float f[4] = {v4.x, v4.y, v4.z, v4.w};
#pragma unroll
        for (int j = 0; j < 4; j++) {
            unsigned u = okey(f[j]);
            int bin = -1;
            if (pass == 0) bin = (int)(u >> 21);
            else if (pass == 1) { if ((u >> 21) == (prefix >> 21)) bin = (int)((u >> 10) & 0x7FFu); }
            else { if ((u >> 10) == (prefix >> 10)) bin = (int)(u & 0x3FFu); }
            unsigned mask = __match_any_sync(0xffffffffu, bin);
            if (bin >= 0 && ((threadIdx.x & 31) == (__ffs(mask) - 1)))
                atomicAdd(&hist[bin], (unsigned)__popc(mask));
        }
    }
    __syncthreads();
    for (int i = threadIdx.x; i < 2048; i += 256)
        if (hist[i]) atomicAdd(&g_hist2[b * 2048 + i], hist[i]);
}

__global__ void sel_step_g(float* __restrict__ red, int pass) {
    int b = blockIdx.x;
    int t = threadIdx.x;  // 256
    unsigned* hist = g_hist2 + (size_t)b * 2048;
    unsigned loc[8];
    unsigned psum = 0;
#pragma unroll
    for (int q = 0; q < 8; q++) { loc[q] = hist[t * 8 + q]; psum += loc[q]; }
    __shared__ unsigned sh[256];
    __shared__ int s_sel;
    __shared__ unsigned s_cum;
    sh[t] = psum;
    __syncthreads();
    if (t == 0) {
        int r = g_rank[b];
        unsigned cum = 0;
        int ti = 0;
        for (; ti < 255; ti++) {
            if (cum + sh[ti] > (unsigned)r) break;
            cum += sh[ti];
        }
        s_sel = ti;
        s_cum = cum;
    }
    __syncthreads();
    if (t == s_sel) {
        int r = g_rank[b];
        unsigned cum = s_cum;
        int bin = t * 8;
#pragma unroll
        for (int q = 0; q < 8; q++) {
            if (cum + loc[q] > (unsigned)r) { bin = t * 8 + q; break; }
            cum += loc[q];
        }
        g_rank[b] = r - (int)cum;
        unsigned p;
        if (pass == 0) p = (unsigned)bin << 21;
        else if (pass == 1) p = g_prefix[b] | ((unsigned)bin << 10);
        else p = g_prefix[b] | (unsigned)bin;
        g_prefix[b] = p;
        if (pass == 2) red[b * 8 + 2] = __uint_as_float(p);
    }
    __syncthreads();
    for (int i = t; i < 2048; i += 256) hist[i] = 0;  // re-zero for replay
}

// ---------------- kept-sum + full-sum of exp(2(e-m)) in one pass ------------
__global__ void csum2_kernel(const float* __restrict__ es, const float* __restrict__ red,
                             float* __restrict__ part) {
    int b = blockIdx.y, seg = blockIdx.x;
    unsigned thr = __float_as_uint(red[b * 8 + 2]);
    float m = okey_dec(g_maxkey[b]);
    const float4* p4 = reinterpret_cast<const float4*>(es + (size_t)b * NN + seg * 2048);
    float sk = 0.f, sz = 0.f;
    for (int i = threadIdx.x; i < 512; i += 256) {
        float4 v4 = p4[i];
        float f[4] = {v4.x, v4.y, v4.z, v4.w};
#pragma unroll
        for (int j = 0; j < 4; j++) {
            float e = __expf(2.f * (f[j] - m));
            sz += e;
            if (okey(f[j]) >= thr) sk += e;
        }
    }
    sk = blockReduceF(sk, SumOp(), 0.f);
    sz = blockReduceF(sz, SumOp(), 0.f);
    if (threadIdx.x == 0) {
        part[b * 256 + seg] = sk;
        part[b * 256 + 128 + seg] = sz;
    }
}

__global__ void reduce2_kernel(const float* __restrict__ part, float* __restrict__ red) {
    int b = blockIdx.x;
    float v1 = part[b * 256 + threadIdx.x];
    float v2 = part[b * 256 + 128 + threadIdx.x];
    v1 = blockReduceF(v1, SumOp(), 0.f);
    v2 = blockReduceF(v2, SumOp(), 0.f);
    if (threadIdx.x == 0) {
        red[b * 8 + 3] = v1;  // S_kept
        red[b * 8 + 4] = v2;  // Z
    }
}

__global__ void adj_write(const float* __restrict__ es, const float* __restrict__ red,
                          float* __restrict__ adj) {
    size_t i4 = (size_t)blockIdx.x * blockDim.x + threadIdx.x;   // float4 index
    int b = (int)(i4 / (NN / 4));
    unsigned thr = __float_as_uint(red[b * 8 + 2]);
    float m = okey_dec(g_maxkey[b]);
    float inv = 1.f / (red[b * 8 + 3] + red[b * 8 + 4] * 1e-12f);
    float4 v4 = reinterpret_cast<const float4*>(es)[i4];
    float f[4] = {v4.x, v4.y, v4.z, v4.w};
    float r[4];
#pragma unroll
    for (int j = 0; j < 4; j++)
        r[j] = (okey(f[j]) >= thr) ? __expf(2.f * (f[j] - m)) * inv : 0.f;
    reinterpret_cast<float4*>(adj)[i4] = make_float4(r[0], r[1], r[2], r[3]);
}

// ---------------- batchnorm ----------------
__global__ void bn_stats(const float* __restrict__ h, int C, float* __restrict__ stats) {
    int c = blockIdx.x;
    double s = 0.0, s2 = 0.0;
    for (int r = threadIdx.x; r < cB * cN; r += blockDim.x) {
        double v = (double)h[(size_t)r * C + c];
        s += v;
        s2 += v * v;
    }
    s = blockReduceD(s);
    s2 = blockReduceD(s2);
    if (threadIdx.x == 0) {
        double m = s / (cB * cN);
        double var = s2 / (cB * cN) - m * m;
        stats[2 * c] = (float)m;
        stats[2 * c + 1] = (float)rsqrt(var + 1e-5);
    }
}

// fold bn stats + gamma/beta into per-channel scale/shift
__global__ void bn_prep(const float* __restrict__ stats, const float* __restrict__ ga,
                        const float* __restrict__ be, float* __restrict__ sc,
                        float* __restrict__ sh, int C) {
    int c = blockIdx.x * blockDim.x + threadIdx.x;
    if (c < C) {
        float s = stats[2 * c + 1] * ga[c];
        sc[c] = s;
        sh[c] = be[c] - stats[2 * c] * s;
    }
}

// ---------------- final ----------------
__global__ void final_kernel(const float* __restrict__ g2, const float* __restrict__ stats,
                             const float* __restrict__ ga, const float* __restrict__ be,
                             const float* __restrict__ clsw, const float* __restrict__ clsb,
                             float* __restrict__ out) {
    int b = blockIdx.x, c = threadIdx.x;
    float m = stats[2 * c], is = stats[2 * c + 1], gg = ga[c], bb = be[c];
    float s = 0.f;
    for (int n = 0; n < cN; n++) {
        float v = g2[((size_t)(b * cN + n)) * cOUT + c];
        v = (v - m) * is * gg + bb;
        s += fmaxf(v, 0.f);
    }
    __shared__ float feat[cOUT];
    feat[c] = s * (1.f / cN);
    __syncthreads();
    if (c < cNC) {
        float o = clsb[c];
        for (int q = 0; q < cOUT; q++) o += feat[q] * clsw[c * cOUT + q];
        out[b * cNC + c] = o;
    }
}

// ---------------- launch ----------------
extern "C" void kernel_launch(void* const* d_in, const int* in_sizes, int n_in,
                              void* d_out, int out_size) {
    const float* x      = (const float*)d_in[0];
    const float* Wg     = (const float*)d_in[1];
    const float* attn_w = (const float*)d_in[2];
    const float* W1     = (const float*)d_in[3];
    const float* b1     = (const float*)d_in[4];
    const float* w2     = (const float*)d_in[5];
    const float* b2     = (const float*)d_in[6];
    const float* gc1_w  = (const float*)d_in[7];
    const float* gc1_b  = (const float*)d_in[8];
    const float* bn1g   = (const float*)d_in[9];
    const float* bn1b   = (const float*)d_in[10];
    const float* gc2_w  = (const float*)d_in[11];
    const float* gc2_b  = (const float*)d_in[12];
    const float* bn2g   = (const float*)d_in[13];
    const float* bn2b   = (const float*)d_in[14];
    const float* clsw   = (const float*)d_in[15];
    const float* clsb   = (const float*)d_in[16];

    float* buf = nullptr;
    cudaGetSymbolAddress((void**)&buf, g_buf);
    float* hp    = buf + OFF_HP;
    float* alpha = buf + OFF_ALPHA;
    float* nf    = buf + OFF_NF;
    float* pi    = buf + OFF_PI;
    float* pj    = buf + OFF_PJ;
    float* es    = buf + OFF_ES;
    float* adj   = buf + OFF_ADJ;
    float* t1    = buf + OFF_H1;
    float* g1    = buf + OFF_G1;
    float* t2    = buf + OFF_H2;
    float* g2    = buf + OFF_G2;
    float* si    = buf + OFF_SI;
    float* sj    = buf + OFF_SJ;
    float* part  = buf + OFF_PART;
    float* red   = buf + OFF_RED;
    float* bn1s  = buf + OFF_BN1;
    float* bn2s  = buf + OFF_BN2;
    float* bnsc  = buf + OFF_BNP;
    float* bnsh  = buf + OFF_BNP + cHID;

    typedef long long ll;

    // 0) init select state (before edge_kernel's atomicMax)
    sel_init<<<16, 256>>>();
    // 1) hp = x @ Wg^T
    gemm_tc<<<dim3(cF / 64, (cB * cN) / 64, 1), 256>>>(
        x, cF, 0, 0, Wg, cF, 0, 0, hp, cF, 0, 0,
        cB * cN, cF, cF, 1, nullptr, 0, 1);
    // 2) s_i, s_j
    si_sj2<<<cB * cN, 256>>>(hp, attn_w, si, sj);
    // 3) attention softmax
    attn_softmax<<<cB * cH * cN, 256>>>(si, sj, alpha);
    // 4) node_feats = alpha @ hp (batched b,h)
    gemm_tc<<<dim3(cDH / 64, cN / 64, cB * cH), 256>>>(
        alpha, cN, (ll)cH * NN, (ll)NN,
        hp, cF, (ll)cN * cF, (ll)cDH,
        nf, cF, (ll)cN * cF, (ll)cDH,
        cN, cDH, cN, cH, nullptr, 0, 0);
    // 5) pi/pj fused (grid.z = 2)
    gemm_tc<<<dim3(cAH / 64, (cB * cN) / 64, 2), 256>>>(
        nf, cF, 0, 0,
        W1, 2 * cF, 0, (ll)cF,
        pi, cAH, 0, (ll)cB * cN * cAH,
        cB * cN, cAH, cF, 2, b1, 1, 1);
    // 6) edge scores + per-batch max
    edge_kernel<<<dim3(cN / 64, cN / 64, cB), 256>>>(pi, pj, w2, b2, es);
    // 7) exact order statistic: 3 radix passes (11/11/10 bits, smem hist)
    for (int p = 0; p < 3; p++) {
        sel_hist_g<<<dim3(64, cB), 256>>>(es, p);
        sel_step_g<<<cB, 256>>>(red, p);
    }
    // 8) kept-sum + Z; adjacency write
    csum2_kernel<<<dim3(128, cB), 256>>>(es, red, part);
    reduce2_kernel<<<cB, 128>>>(part, red);
    adj_write<<<(cB * NN / 4) / 256, 256>>>(es, red, adj);
    // 9) stage 1 (reassociated): t1 = nf @ gc1_w^T ; g1 = adj @ t1 + gc1_b
    gemm_tc<<<dim3(cHID / 64, (cB * cN) / 64, 1), 256>>>(
        nf, cF, 0, 0, gc1_w, cF, 0, 0, t1, cHID, 0, 0,
        cB * cN, cHID, cF, 1, nullptr, 0, 1);
    gemm_tc<<<dim3(cHID / 64, cN / 64, cB), 256>>>(
        adj, cN, (ll)NN, 0,
        t1, cHID, (ll)cN * cHID, 0,
        g1, cHID, (ll)cN * cHID, 0,
        cN, cHID, cN, 1, gc1_b, 1, 0);
    bn_stats<<<cHID, 256>>>(g1, cHID, bn1s);
    bn_prep<<<2, 256>>>(bn1s, bn1g, bn1b, bnsc, bnsh, cHID);
    // 10) stage 2 (reassociated): t2 = bnrelu(g1) @ gc2_w^T via CLONE kernel,
    //     then g2 = adj @ t2 + gc2_b via the untouched gemm_tc
    gemm_tc_bn<<<dim3(cOUT / 64, (cB * cN) / 64), 256>>>(
        g1, cHID, gc2_w, cHID, t2, cOUT,
        cB * cN, cOUT, cHID, bnsc, bnsh);
    gemm_tc<<<dim3(cOUT / 64, cN / 64, cB), 256>>>(
        adj, cN, (ll)NN, 0,
        t2, cOUT, (ll)cN * cOUT, 0,
        g2, cOUT, (ll)cN * cOUT, 0,
        cN, cOUT, cN, 1, gc2_b, 1, 0);
    bn_stats<<<cOUT, 256>>>(g2, cOUT, bn2s);
    // 11) final
    final_kernel<<<cB, 128>>>(g2, bn2s, bn2g, bn2b, clsw, clsb, (float*)d_out);
}